// round 5
// baseline (speedup 1.0000x reference)
#include <cuda_runtime.h>
#include <math.h>

#define BB   8
#define CC   128
#define OO   128
#define HH   64
#define WW   64
#define HW   4096
#define NPIX 32768           // B*H*W
#define CKK  1152            // C*9
#define NOM  27              // 3*K2 channels of the offset/mask conv
#define CCH  32              // channel chunk staged in static smem
#define CHW_ELEMS (NOM*CCH*9)  // 7776 floats = 31.1 KB

// ---------------- device scratch (allocation-free rule: static __device__) -----------
__device__ float4  g_w4[BB * 9 * HW];     // 4 bilinear weights (mask+validity folded)
__device__ ushort4 g_idx[BB * 9 * HW];    // 4 pre-clamped linear offsets into a 64x64 plane

// ============================================================================
// Kernel 1: 3x3 conv producing 27 channels per pixel, then transform into
// per-(b,k,p) bilinear sampling weights (+softmax mask) and clamped corner
// offsets. 128-thread blocks (256 blocks total) so ~7 blocks/SM can co-reside
// (smem-limited) -> ~28 warps/SM vs 8 before.
// ============================================================================
__global__ __launch_bounds__(128)
void om_kernel(const float* __restrict__ x, const float* __restrict__ w_om,
               const float* __restrict__ b_om) {
    __shared__ float s_w[CHW_ELEMS];   // [oc][c_local][t] = [(oc*CCH + cl)*9 + t]
    const int tid = threadIdx.x;

    const int bp = blockIdx.x * 128 + tid;
    const int b = bp >> 12;
    const int p = bp & 4095;
    const int y = p >> 6;
    const int xx = p & 63;

    const float* __restrict__ xb = x + (size_t)(b * CC) * HW;

    float acc[NOM];
#pragma unroll
    for (int i = 0; i < NOM; ++i) acc[i] = 0.f;

    for (int c0 = 0; c0 < CC; c0 += CCH) {
        __syncthreads();
        for (int i = tid; i < CHW_ELEMS; i += 128) {
            const int oc = i / (CCH * 9);
            const int rem = i - oc * (CCH * 9);
            const int cl = rem / 9;
            const int t = rem - cl * 9;
            s_w[i] = w_om[(size_t)oc * CKK + (c0 + cl) * 9 + t];
        }
        __syncthreads();

        for (int cl = 0; cl < CCH; ++cl) {
            const float* __restrict__ xc = xb + (c0 + cl) * HW;
            float v[9];
#pragma unroll
            for (int t = 0; t < 9; ++t) {
                const int yy = y + t / 3 - 1;
                const int xc2 = xx + t % 3 - 1;
                const bool ok = (yy >= 0) & (yy < HH) & (xc2 >= 0) & (xc2 < WW);
                v[t] = ok ? __ldg(xc + yy * WW + xc2) : 0.f;
            }
            const float* wc = s_w + cl * 9;
#pragma unroll
            for (int oc = 0; oc < NOM; ++oc) {
                const float* wr = wc + oc * (CCH * 9);
#pragma unroll
                for (int t = 0; t < 9; ++t) acc[oc] = fmaf(wr[t], v[t], acc[oc]);
            }
        }
    }
#pragma unroll
    for (int oc = 0; oc < NOM; ++oc) acc[oc] += __ldg(b_om + oc);

    // softmax over the 9 mask channels (18..26)
    float mx = acc[18];
#pragma unroll
    for (int k = 1; k < 9; ++k) mx = fmaxf(mx, acc[18 + k]);
    float e[9], s = 0.f;
#pragma unroll
    for (int k = 0; k < 9; ++k) { e[k] = expf(acc[18 + k] - mx); s += e[k]; }
    const float inv = 1.f / s;

#pragma unroll
    for (int k = 0; k < 9; ++k) {
        const float m = e[k] * inv;
        // offset channel 2k = dy, 2k+1 = dx  (concat(o1,o2) == om[0:18] directly)
        const float py = (float)(y - 1 + k / 3) + acc[2 * k];
        const float px = (float)(xx - 1 + k % 3) + acc[2 * k + 1];
        const float fy = floorf(py), fx = floorf(px);
        const int y0 = (int)fy, x0 = (int)fx;
        const float wy1 = py - fy, wx1 = px - fx;
        const float wy0 = 1.f - wy1, wx0 = 1.f - wx1;
        const bool vy0 = (y0 >= 0) & (y0 < HH);
        const bool vy1 = (y0 >= -1) & (y0 < HH - 1);
        const bool vx0 = (x0 >= 0) & (x0 < WW);
        const bool vx1 = (x0 >= -1) & (x0 < WW - 1);
        float4 w4;
        w4.x = (vy0 & vx0) ? wy0 * wx0 * m : 0.f;
        w4.y = (vy0 & vx1) ? wy0 * wx1 * m : 0.f;
        w4.z = (vy1 & vx0) ? wy1 * wx0 * m : 0.f;
        w4.w = (vy1 & vx1) ? wy1 * wx1 * m : 0.f;
        const int y0c = min(max(y0, 0), HH - 1);
        const int y1c = min(max(y0 + 1, 0), HH - 1);
        const int x0c = min(max(x0, 0), WW - 1);
        const int x1c = min(max(x0 + 1, 0), WW - 1);
        ushort4 s4;
        s4.x = (unsigned short)(y0c * WW + x0c);
        s4.y = (unsigned short)(y0c * WW + x1c);
        s4.z = (unsigned short)(y1c * WW + x0c);
        s4.w = (unsigned short)(y1c * WW + x1c);
        const int idx = (b * 9 + k) * HW + p;
        g_w4[idx] = w4;
        g_idx[idx] = s4;
    }
}

// ============================================================================
// Kernel 2: fused SGEMM  out[o][bp] = W2[128x1152] * V[1152x32768] + bias
// where V is materialized ON THE FLY in the B-tile producer via bilinear
// gathers (x + g_w4/g_idx are L1/L2-resident). 128x128 tile, BK=16,
// double-buffered smem, 8x8 register microtile.
// ============================================================================
#define BK 16
#define AST 132   // padded A-tile stride; MUST be a multiple of 4 (float4 LDS.128)

__device__ __forceinline__ float sample_one(const float* __restrict__ xb,
                                            int bimg9, int row, int pcol) {
    const int c = row / 9;
    const int k = row - c * 9;
    const int t = (bimg9 + k) * HW + pcol;
    const float4 w = __ldg(&g_w4[t]);
    const ushort4 s4 = __ldg(&g_idx[t]);
    const float* __restrict__ xc = xb + c * HW;
    return w.x * __ldg(xc + s4.x) + w.y * __ldg(xc + s4.y)
         + w.z * __ldg(xc + s4.z) + w.w * __ldg(xc + s4.w);
}

__global__ __launch_bounds__(256)
void gemm_kernel(const float* __restrict__ x,
                 const float* __restrict__ Wt,    // weight as [128][1152]
                 const float* __restrict__ bias,
                 float* __restrict__ out) {
    __shared__ float As[2][BK * AST];
    __shared__ float Bs[2][BK * 128];

    const int tid = threadIdx.x;
    const int tx = tid & 15;
    const int ty = tid >> 4;
    const int n0 = blockIdx.x * 128;

    // loader coordinates
    const int ra = tid >> 2;        // 0..63  (row of A; +64 for second load)
    const int qa = tid & 3;         // float4 slot within the 16-wide k chunk
    const int rb = tid >> 5;        // 0..7   (row of B; +8 for second load)
    const int qb = tid & 31;        // float4 column

    const int bimg = n0 >> 12;                 // whole tile within one image
    const int bimg9 = bimg * 9;
    const int pcol = (n0 & 4095) + qb * 4;     // first of this thread's 4 columns
    const float* __restrict__ xb = x + (size_t)(bimg * CC) * HW;

    float acc[8][8];
#pragma unroll
    for (int i = 0; i < 8; ++i)
#pragma unroll
        for (int j = 0; j < 8; ++j) acc[i][j] = 0.f;

    // ---- prime stage 0 ----
    {
        const int kt = 0;
        float4 a0 = *(const float4*)(Wt + (size_t)ra * CKK + kt + qa * 4);
        float4 a1 = *(const float4*)(Wt + (size_t)(ra + 64) * CKK + kt + qa * 4);
        float4 b0, b1;
        b0.x = sample_one(xb, bimg9, kt + rb, pcol + 0);
        b0.y = sample_one(xb, bimg9, kt + rb, pcol + 1);
        b0.z = sample_one(xb, bimg9, kt + rb, pcol + 2);
        b0.w = sample_one(xb, bimg9, kt + rb, pcol + 3);
        b1.x = sample_one(xb, bimg9, kt + rb + 8, pcol + 0);
        b1.y = sample_one(xb, bimg9, kt + rb + 8, pcol + 1);
        b1.z = sample_one(xb, bimg9, kt + rb + 8, pcol + 2);
        b1.w = sample_one(xb, bimg9, kt + rb + 8, pcol + 3);
        As[0][(qa * 4 + 0) * AST + ra] = a0.x;
        As[0][(qa * 4 + 1) * AST + ra] = a0.y;
        As[0][(qa * 4 + 2) * AST + ra] = a0.z;
        As[0][(qa * 4 + 3) * AST + ra] = a0.w;
        As[0][(qa * 4 + 0) * AST + ra + 64] = a1.x;
        As[0][(qa * 4 + 1) * AST + ra + 64] = a1.y;
        As[0][(qa * 4 + 2) * AST + ra + 64] = a1.z;
        As[0][(qa * 4 + 3) * AST + ra + 64] = a1.w;
        *(float4*)&Bs[0][rb * 128 + qb * 4] = b0;
        *(float4*)&Bs[0][(rb + 8) * 128 + qb * 4] = b1;
    }
    __syncthreads();

    int s = 0;
    const int NIT = CKK / BK;   // 72
    for (int it = 0; it < NIT; ++it) {
        float4 a0n, a1n, b0n, b1n;
        if (it < NIT - 1) {
            const int kt = (it + 1) * BK;
            a0n = *(const float4*)(Wt + (size_t)ra * CKK + kt + qa * 4);
            a1n = *(const float4*)(Wt + (size_t)(ra + 64) * CKK + kt + qa * 4);
            b0n.x = sample_one(xb, bimg9, kt + rb, pcol + 0);
            b0n.y = sample_one(xb, bimg9, kt + rb, pcol + 1);
            b0n.z = sample_one(xb, bimg9, kt + rb, pcol + 2);
            b0n.w = sample_one(xb, bimg9, kt + rb, pcol + 3);
            b1n.x = sample_one(xb, bimg9, kt + rb + 8, pcol + 0);
            b1n.y = sample_one(xb, bimg9, kt + rb + 8, pcol + 1);
            b1n.z = sample_one(xb, bimg9, kt + rb + 8, pcol + 2);
            b1n.w = sample_one(xb, bimg9, kt + rb + 8, pcol + 3);
        }
#pragma unroll
        for (int k = 0; k < BK; ++k) {
            const float4 af0 = *(const float4*)&As[s][k * AST + ty * 8];
            const float4 af1 = *(const float4*)&As[s][k * AST + ty * 8 + 4];
            const float4 bf0 = *(const float4*)&Bs[s][k * 128 + tx * 8];
            const float4 bf1 = *(const float4*)&Bs[s][k * 128 + tx * 8 + 4];
            const float a[8] = {af0.x, af0.y, af0.z, af0.w, af1.x, af1.y, af1.z, af1.w};
            const float bq[8] = {bf0.x, bf0.y, bf0.z, bf0.w, bf1.x, bf1.y, bf1.z, bf1.w};
#pragma unroll
            for (int i = 0; i < 8; ++i)
#pragma unroll
                for (int j = 0; j < 8; ++j)
                    acc[i][j] = fmaf(a[i], bq[j], acc[i][j]);
        }
        if (it < NIT - 1) {
            const int s2 = s ^ 1;
            As[s2][(qa * 4 + 0) * AST + ra] = a0n.x;
            As[s2][(qa * 4 + 1) * AST + ra] = a0n.y;
            As[s2][(qa * 4 + 2) * AST + ra] = a0n.z;
            As[s2][(qa * 4 + 3) * AST + ra] = a0n.w;
            As[s2][(qa * 4 + 0) * AST + ra + 64] = a1n.x;
            As[s2][(qa * 4 + 1) * AST + ra + 64] = a1n.y;
            As[s2][(qa * 4 + 2) * AST + ra + 64] = a1n.z;
            As[s2][(qa * 4 + 3) * AST + ra + 64] = a1n.w;
            *(float4*)&Bs[s2][rb * 128 + qb * 4] = b0n;
            *(float4*)&Bs[s2][(rb + 8) * 128 + qb * 4] = b1n;
        }
        __syncthreads();
        s ^= 1;
    }

    // ---- epilogue: add bias, write out[b][o][p] ----
    const int p0 = n0 & 4095;
#pragma unroll
    for (int i = 0; i < 8; ++i) {
        const int o = ty * 8 + i;
        const float bv = __ldg(bias + o);
        float* op = out + ((size_t)(bimg * OO + o)) * HW + p0 + tx * 8;
        float4 r0, r1;
        r0.x = acc[i][0] + bv; r0.y = acc[i][1] + bv;
        r0.z = acc[i][2] + bv; r0.w = acc[i][3] + bv;
        r1.x = acc[i][4] + bv; r1.y = acc[i][5] + bv;
        r1.z = acc[i][6] + bv; r1.w = acc[i][7] + bv;
        *(float4*)op = r0;
        *(float4*)(op + 4) = r1;
    }
}

// ============================================================================
extern "C" void kernel_launch(void* const* d_in, const int* in_sizes, int n_in,
                              void* d_out, int out_size) {
    const float* x      = (const float*)d_in[0];   // (8,128,64,64)
    const float* w_om   = (const float*)d_in[1];   // (27,128,3,3)
    const float* b_om   = (const float*)d_in[2];   // (27,)
    const float* weight = (const float*)d_in[3];   // (128,128,3,3) -> [128][1152]
    const float* bias   = (const float*)d_in[4];   // (128,)
    float* out = (float*)d_out;                    // (8,128,64,64)

    om_kernel<<<NPIX / 128, 128>>>(x, w_om, b_om);
    gemm_kernel<<<NPIX / 128, 256>>>(x, weight, bias, out);
}

// round 7
// speedup vs baseline: 1.6698x; 1.6698x over previous
#include <cuda_runtime.h>
#include <cuda_bf16.h>
#include <cstdint>
#include <math.h>

#define BB   8
#define CC   128
#define OO   128
#define HH   64
#define WW   64
#define HW   4096
#define NPIX 32768
#define CKK  1152
#define NOM  27
#define NCH  4                 // channel chunks for om conv
#define CCH  32                // channels per chunk
#define CHW_ELEMS (NOM*CCH*9)  // 7776 floats = 31.1 KB

// ---------------- device scratch (allocation-free rule) ----------------
__device__ __align__(16) unsigned short g_Whi[OO * CKK];  // bf16 hi part of weight
__device__ __align__(16) unsigned short g_Wlo[OO * CKK];  // bf16 lo part
__device__ float   g_part[NCH * NOM * NPIX];              // om conv partial sums
__device__ float4  g_w4[BB * 9 * HW];                     // bilinear weights (mask+validity)
__device__ ushort4 g_idx[BB * 9 * HW];                    // pre-clamped offsets in 64x64 plane

// ============================================================================
// Kernel 0: split weight into bf16 hi/lo parts
// ============================================================================
__global__ __launch_bounds__(256)
void prep_w(const float* __restrict__ w) {
    const int i = blockIdx.x * 256 + threadIdx.x;
    if (i < OO * CKK) {
        const float v = w[i];
        const __nv_bfloat16 hb = __float2bfloat16(v);
        const float lo = v - __bfloat162float(hb);
        g_Whi[i] = __bfloat16_as_ushort(hb);
        g_Wlo[i] = __bfloat16_as_ushort(__float2bfloat16(lo));
    }
}

// ============================================================================
// Kernel 1a: om conv partials — grid (128 px-blocks, 4 c-chunks), 256 thr
// ============================================================================
__global__ __launch_bounds__(256)
void om_partial(const float* __restrict__ x, const float* __restrict__ w_om) {
    __shared__ float s_w[CHW_ELEMS];
    const int tid = threadIdx.x;
    const int chunk = blockIdx.y;
    const int c0 = chunk * CCH;

    for (int i = tid; i < CHW_ELEMS; i += 256) {
        const int oc = i / (CCH * 9);
        const int rem = i - oc * (CCH * 9);
        const int cl = rem / 9;
        const int t = rem - cl * 9;
        s_w[i] = w_om[(size_t)oc * CKK + (c0 + cl) * 9 + t];
    }
    __syncthreads();

    const int bp = blockIdx.x * 256 + tid;
    const int b = bp >> 12;
    const int p = bp & 4095;
    const int y = p >> 6;
    const int xx = p & 63;
    const float* __restrict__ xb = x + (size_t)(b * CC + c0) * HW;

    float acc[NOM];
#pragma unroll
    for (int i = 0; i < NOM; ++i) acc[i] = 0.f;

    for (int cl = 0; cl < CCH; ++cl) {
        const float* __restrict__ xc = xb + cl * HW;
        float v[9];
#pragma unroll
        for (int t = 0; t < 9; ++t) {
            const int yy = y + t / 3 - 1;
            const int xc2 = xx + t % 3 - 1;
            const bool ok = (yy >= 0) & (yy < HH) & (xc2 >= 0) & (xc2 < WW);
            v[t] = ok ? __ldg(xc + yy * WW + xc2) : 0.f;
        }
        const float* wc = s_w + cl * 9;
#pragma unroll
        for (int oc = 0; oc < NOM; ++oc) {
            const float* wr = wc + oc * (CCH * 9);
#pragma unroll
            for (int t = 0; t < 9; ++t) acc[oc] = fmaf(wr[t], v[t], acc[oc]);
        }
    }
#pragma unroll
    for (int oc = 0; oc < NOM; ++oc)
        g_part[((size_t)chunk * NOM + oc) * NPIX + bp] = acc[oc];
}

// ============================================================================
// Kernel 1b: reduce partials, softmax mask, emit bilinear weights + offsets
// ============================================================================
__global__ __launch_bounds__(256)
void om_final(const float* __restrict__ b_om) {
    const int bp = blockIdx.x * 256 + threadIdx.x;
    const int b = bp >> 12;
    const int p = bp & 4095;
    const int y = p >> 6;
    const int xx = p & 63;

    float acc[NOM];
#pragma unroll
    for (int oc = 0; oc < NOM; ++oc) {
        float a = __ldg(b_om + oc);
#pragma unroll
        for (int ch = 0; ch < NCH; ++ch)
            a += g_part[((size_t)ch * NOM + oc) * NPIX + bp];
        acc[oc] = a;
    }

    float mx = acc[18];
#pragma unroll
    for (int k = 1; k < 9; ++k) mx = fmaxf(mx, acc[18 + k]);
    float e[9], s = 0.f;
#pragma unroll
    for (int k = 0; k < 9; ++k) { e[k] = expf(acc[18 + k] - mx); s += e[k]; }
    const float inv = 1.f / s;

#pragma unroll
    for (int k = 0; k < 9; ++k) {
        const float m = e[k] * inv;
        const float py = (float)(y - 1 + k / 3) + acc[2 * k];
        const float px = (float)(xx - 1 + k % 3) + acc[2 * k + 1];
        const float fy = floorf(py), fx = floorf(px);
        const int y0 = (int)fy, x0 = (int)fx;
        const float wy1 = py - fy, wx1 = px - fx;
        const float wy0 = 1.f - wy1, wx0 = 1.f - wx1;
        const bool vy0 = (y0 >= 0) & (y0 < HH);
        const bool vy1 = (y0 >= -1) & (y0 < HH - 1);
        const bool vx0 = (x0 >= 0) & (x0 < WW);
        const bool vx1 = (x0 >= -1) & (x0 < WW - 1);
        float4 w4;
        w4.x = (vy0 & vx0) ? wy0 * wx0 * m : 0.f;
        w4.y = (vy0 & vx1) ? wy0 * wx1 * m : 0.f;
        w4.z = (vy1 & vx0) ? wy1 * wx0 * m : 0.f;
        w4.w = (vy1 & vx1) ? wy1 * wx1 * m : 0.f;
        const int y0c = min(max(y0, 0), HH - 1);
        const int y1c = min(max(y0 + 1, 0), HH - 1);
        const int x0c = min(max(x0, 0), WW - 1);
        const int x1c = min(max(x0 + 1, 0), WW - 1);
        ushort4 s4;
        s4.x = (unsigned short)(y0c * WW + x0c);
        s4.y = (unsigned short)(y0c * WW + x1c);
        s4.z = (unsigned short)(y1c * WW + x0c);
        s4.w = (unsigned short)(y1c * WW + x1c);
        const int idx = (b * 9 + k) * HW + p;
        g_w4[idx] = w4;
        g_idx[idx] = s4;
    }
}

// ============================================================================
// Kernel 2: bf16 split-precision tensor-core GEMM via mma.sync.m16n8k16.
// out[o][p] = W[o][ck] * V[ck][p] + bias,  D += Ahi*Bhi + Ahi*Blo + Alo*Bhi.
// CTA tile: 128 o x 128 px, BK=16. B produced on the fly (bilinear gathers).
// Tiles at 48B row stride -> conflict-free ldmatrix.x4.
// ============================================================================
#define BKC  16
#define BSTU 24   // ushorts per tile row (48 bytes)
#define NIT  (CKK / BKC)   // 72

__device__ __forceinline__ uint32_t smem_u32(const void* p) {
    uint32_t a;
    asm("{ .reg .u64 t; cvta.to.shared.u64 t, %1; cvt.u32.u64 %0, t; }" : "=r"(a) : "l"(p));
    return a;
}
__device__ __forceinline__ void ldm_x4(uint32_t* r, uint32_t addr) {
    asm volatile("ldmatrix.sync.aligned.m8n8.x4.shared.b16 {%0,%1,%2,%3}, [%4];"
                 : "=r"(r[0]), "=r"(r[1]), "=r"(r[2]), "=r"(r[3]) : "r"(addr));
}
__device__ __forceinline__ void mma_bf16(float* c, const uint32_t* a, uint32_t b0, uint32_t b1) {
    asm volatile("mma.sync.aligned.m16n8k16.row.col.f32.bf16.bf16.f32 "
                 "{%0,%1,%2,%3}, {%4,%5,%6,%7}, {%8,%9}, {%0,%1,%2,%3};"
                 : "+f"(c[0]), "+f"(c[1]), "+f"(c[2]), "+f"(c[3])
                 : "r"(a[0]), "r"(a[1]), "r"(a[2]), "r"(a[3]), "r"(b0), "r"(b1));
}

__global__ __launch_bounds__(256, 2)
void gemm_mma(const float* __restrict__ x, const float* __restrict__ bias,
              float* __restrict__ out) {
    __shared__ __align__(16) unsigned short Ahi[128 * BSTU];
    __shared__ __align__(16) unsigned short Alo[128 * BSTU];
    __shared__ __align__(16) unsigned short Bhi[128 * BSTU];
    __shared__ __align__(16) unsigned short Blo[128 * BSTU];

    const int tid = threadIdx.x;
    const int wid = tid >> 5;
    const int lid = tid & 31;
    const int n0 = blockIdx.x * 128;

    const int bimg = n0 >> 12;
    const int p0 = n0 & 4095;
    const int bimg9 = bimg * 9;
    const float* __restrict__ xb = x + (size_t)(bimg * CC) * HW;

    // producer coords
    const int arow = tid >> 1;          // A: 128 rows x 2 halves
    const int ahalf = tid & 1;
    const int px = tid & 127;           // B: 128 px x 2 halves of 16 ck
    const int bh = tid >> 7;
    const int pj = p0 + px;

    // ldmatrix lane addresses (bytes)
    const int o0 = wid * 16;
    const uint32_t aAddrOff =
        (uint32_t)((o0 + (lid & 7) + ((lid >> 3) & 1) * 8) * 48 + ((lid >> 4) & 1) * 16);
    const uint32_t aHi = smem_u32(Ahi) + aAddrOff;
    const uint32_t aLo = smem_u32(Alo) + aAddrOff;
    const uint32_t bAddrOff =
        (uint32_t)(((lid & 7) + ((lid >> 4) & 1) * 8) * 48 + ((lid >> 3) & 1) * 16);
    const uint32_t bHiBase = smem_u32(Bhi) + bAddrOff;
    const uint32_t bLoBase = smem_u32(Blo) + bAddrOff;

    float acc[16][4];
#pragma unroll
    for (int i = 0; i < 16; ++i)
#pragma unroll
        for (int j = 0; j < 4; ++j) acc[i][j] = 0.f;

    for (int it = 0; it < NIT; ++it) {
        const int ck0 = it * BKC;

        // ---- produce A tiles (hi/lo): one uint4 (8 bf16) per thread per tile ----
        {
            const size_t gi = (size_t)arow * CKK + ck0 + ahalf * 8;
            const uint4 ah = *(const uint4*)(g_Whi + gi);
            const uint4 al = *(const uint4*)(g_Wlo + gi);
            *(uint4*)(Ahi + arow * BSTU + ahalf * 8) = ah;
            *(uint4*)(Alo + arow * BSTU + ahalf * 8) = al;
        }

        // ---- produce B tile: sample 8 ck for this px, split bf16 hi/lo ----
        {
            int ck = ck0 + bh * 8;
            int c = (ck * 7282) >> 16;   // ck/9 for ck<1296
            int k = ck - c * 9;
            uint32_t hw_[4], lw_[4];
            unsigned short hu[8], lu[8];
#pragma unroll
            for (int j = 0; j < 8; ++j) {
                const int t = (bimg9 + k) * HW + pj;
                const float4 w = __ldg(&g_w4[t]);
                const ushort4 s4 = __ldg(&g_idx[t]);
                const float* __restrict__ xc = xb + c * HW;
                const float v = w.x * __ldg(xc + s4.x) + w.y * __ldg(xc + s4.y)
                              + w.z * __ldg(xc + s4.z) + w.w * __ldg(xc + s4.w);
                const __nv_bfloat16 hb = __float2bfloat16(v);
                hu[j] = __bfloat16_as_ushort(hb);
                lu[j] = __bfloat16_as_ushort(__float2bfloat16(v - __bfloat162float(hb)));
                if (++k == 9) { k = 0; ++c; }
            }
#pragma unroll
            for (int j = 0; j < 4; ++j) {
                hw_[j] = (uint32_t)hu[2 * j] | ((uint32_t)hu[2 * j + 1] << 16);
                lw_[j] = (uint32_t)lu[2 * j] | ((uint32_t)lu[2 * j + 1] << 16);
            }
            *(uint4*)(Bhi + px * BSTU + bh * 8) = make_uint4(hw_[0], hw_[1], hw_[2], hw_[3]);
            *(uint4*)(Blo + px * BSTU + bh * 8) = make_uint4(lw_[0], lw_[1], lw_[2], lw_[3]);
        }

        __syncthreads();

        // ---- consume: A frags then 8 pair-tiles of B ----
        uint32_t fAh[4], fAl[4];
        ldm_x4(fAh, aHi);
        ldm_x4(fAl, aLo);

#pragma unroll
        for (int pt = 0; pt < 8; ++pt) {
            uint32_t fBh[4], fBl[4];
            ldm_x4(fBh, bHiBase + pt * 16 * 48);
            ldm_x4(fBl, bLoBase + pt * 16 * 48);
            // tile 2*pt  (n = pt*16 .. +7):  b regs {0,1}
            mma_bf16(acc[2 * pt], fAh, fBh[0], fBh[1]);
            mma_bf16(acc[2 * pt], fAh, fBl[0], fBl[1]);
            mma_bf16(acc[2 * pt], fAl, fBh[0], fBh[1]);
            // tile 2*pt+1 (n = pt*16+8..+15): b regs {2,3}
            mma_bf16(acc[2 * pt + 1], fAh, fBh[2], fBh[3]);
            mma_bf16(acc[2 * pt + 1], fAh, fBl[2], fBl[3]);
            mma_bf16(acc[2 * pt + 1], fAl, fBh[2], fBh[3]);
        }
        __syncthreads();
    }

    // ---- epilogue: add bias, write out ----
    const int r = lid >> 2;
    const int q = lid & 3;
    const int oA = o0 + r;
    const int oB = o0 + r + 8;
    const float bvA = __ldg(bias + oA);
    const float bvB = __ldg(bias + oB);
    float* baseA = out + ((size_t)(bimg * OO + oA)) * HW + p0 + 2 * q;
    float* baseB = out + ((size_t)(bimg * OO + oB)) * HW + p0 + 2 * q;
#pragma unroll
    for (int nt = 0; nt < 16; ++nt) {
        float2 rA, rB;
        rA.x = acc[nt][0] + bvA; rA.y = acc[nt][1] + bvA;
        rB.x = acc[nt][2] + bvB; rB.y = acc[nt][3] + bvB;
        *(float2*)(baseA + nt * 8) = rA;
        *(float2*)(baseB + nt * 8) = rB;
    }
}

// ============================================================================
extern "C" void kernel_launch(void* const* d_in, const int* in_sizes, int n_in,
                              void* d_out, int out_size) {
    const float* x      = (const float*)d_in[0];   // (8,128,64,64)
    const float* w_om   = (const float*)d_in[1];   // (27,128,3,3)
    const float* b_om   = (const float*)d_in[2];   // (27,)
    const float* weight = (const float*)d_in[3];   // (128,128,3,3)
    const float* bias   = (const float*)d_in[4];   // (128,)
    float* out = (float*)d_out;                    // (8,128,64,64)

    prep_w<<<(OO * CKK + 255) / 256, 256>>>(weight);
    om_partial<<<dim3(NPIX / 256, NCH), 256>>>(x, w_om);
    om_final<<<NPIX / 256, 256>>>(b_om);
    gemm_mma<<<NPIX / 128, 256>>>(x, bias, out);
}

// round 8
// speedup vs baseline: 1.8924x; 1.1333x over previous
#include <cuda_runtime.h>
#include <cuda_bf16.h>
#include <cstdint>
#include <math.h>

#define BB   8
#define CC   128
#define OO   128
#define HH   64
#define WW   64
#define HW   4096
#define NPIX 32768
#define CKK  1152
#define NOM  27
#define NCH  4                 // channel chunks for om conv
#define CCH  32                // channels per chunk
#define CHW_ELEMS (NOM*CCH*9)  // 7776 floats = 31.1 KB

// ---------------- device scratch (allocation-free rule) ----------------
// k-major permuted weights: Wp[o][k*128+c] = w[o][c*9+k], split bf16 hi/lo
__device__ __align__(16) unsigned short g_Wph[OO * CKK];
__device__ __align__(16) unsigned short g_Wpl[OO * CKK];
__device__ float   g_part[NCH * NOM * NPIX];              // om conv partial sums
__device__ float4  g_w4[BB * 9 * HW];                     // bilinear weights (mask+validity)
__device__ ushort4 g_idx[BB * 9 * HW];                    // pre-clamped offsets in 64x64 plane

// ============================================================================
// Kernel 0: permute weight to k-major and split into bf16 hi/lo
// ============================================================================
__global__ __launch_bounds__(256)
void prep_w(const float* __restrict__ w) {
    const int i = blockIdx.x * 256 + threadIdx.x;
    if (i < OO * CKK) {
        const int o = i / CKK;
        const int kk = i - o * CKK;
        const int k = kk >> 7;          // 0..8
        const int c = kk & 127;
        const float v = w[(size_t)o * CKK + c * 9 + k];
        const __nv_bfloat16 hb = __float2bfloat16(v);
        const float lo = v - __bfloat162float(hb);
        g_Wph[i] = __bfloat16_as_ushort(hb);
        g_Wpl[i] = __bfloat16_as_ushort(__float2bfloat16(lo));
    }
}

// ============================================================================
// Kernel 1a: om conv partials — grid (128 px-blocks, 4 c-chunks), 256 thr
// ============================================================================
__global__ __launch_bounds__(256)
void om_partial(const float* __restrict__ x, const float* __restrict__ w_om) {
    __shared__ float s_w[CHW_ELEMS];
    const int tid = threadIdx.x;
    const int chunk = blockIdx.y;
    const int c0 = chunk * CCH;

    for (int i = tid; i < CHW_ELEMS; i += 256) {
        const int oc = i / (CCH * 9);
        const int rem = i - oc * (CCH * 9);
        const int cl = rem / 9;
        const int t = rem - cl * 9;
        s_w[i] = w_om[(size_t)oc * CKK + (c0 + cl) * 9 + t];
    }
    __syncthreads();

    const int bp = blockIdx.x * 256 + tid;
    const int b = bp >> 12;
    const int p = bp & 4095;
    const int y = p >> 6;
    const int xx = p & 63;
    const float* __restrict__ xb = x + (size_t)(b * CC + c0) * HW;

    float acc[NOM];
#pragma unroll
    for (int i = 0; i < NOM; ++i) acc[i] = 0.f;

    for (int cl = 0; cl < CCH; ++cl) {
        const float* __restrict__ xc = xb + cl * HW;
        float v[9];
#pragma unroll
        for (int t = 0; t < 9; ++t) {
            const int yy = y + t / 3 - 1;
            const int xc2 = xx + t % 3 - 1;
            const bool ok = (yy >= 0) & (yy < HH) & (xc2 >= 0) & (xc2 < WW);
            v[t] = ok ? __ldg(xc + yy * WW + xc2) : 0.f;
        }
        const float* wc = s_w + cl * 9;
#pragma unroll
        for (int oc = 0; oc < NOM; ++oc) {
            const float* wr = wc + oc * (CCH * 9);
#pragma unroll
            for (int t = 0; t < 9; ++t) acc[oc] = fmaf(wr[t], v[t], acc[oc]);
        }
    }
#pragma unroll
    for (int oc = 0; oc < NOM; ++oc)
        g_part[((size_t)chunk * NOM + oc) * NPIX + bp] = acc[oc];
}

// ============================================================================
// Kernel 1b: reduce partials, softmax mask, emit bilinear weights + offsets
// ============================================================================
__global__ __launch_bounds__(256)
void om_final(const float* __restrict__ b_om) {
    const int bp = blockIdx.x * 256 + threadIdx.x;
    const int b = bp >> 12;
    const int p = bp & 4095;
    const int y = p >> 6;
    const int xx = p & 63;

    float acc[NOM];
#pragma unroll
    for (int oc = 0; oc < NOM; ++oc) {
        float a = __ldg(b_om + oc);
#pragma unroll
        for (int ch = 0; ch < NCH; ++ch)
            a += g_part[((size_t)ch * NOM + oc) * NPIX + bp];
        acc[oc] = a;
    }

    float mx = acc[18];
#pragma unroll
    for (int k = 1; k < 9; ++k) mx = fmaxf(mx, acc[18 + k]);
    float e[9], s = 0.f;
#pragma unroll
    for (int k = 0; k < 9; ++k) { e[k] = expf(acc[18 + k] - mx); s += e[k]; }
    const float inv = 1.f / s;

#pragma unroll
    for (int k = 0; k < 9; ++k) {
        const float m = e[k] * inv;
        const float py = (float)(y - 1 + k / 3) + acc[2 * k];
        const float px = (float)(xx - 1 + k % 3) + acc[2 * k + 1];
        const float fy = floorf(py), fx = floorf(px);
        const int y0 = (int)fy, x0 = (int)fx;
        const float wy1 = py - fy, wx1 = px - fx;
        const float wy0 = 1.f - wy1, wx0 = 1.f - wx1;
        const bool vy0 = (y0 >= 0) & (y0 < HH);
        const bool vy1 = (y0 >= -1) & (y0 < HH - 1);
        const bool vx0 = (x0 >= 0) & (x0 < WW);
        const bool vx1 = (x0 >= -1) & (x0 < WW - 1);
        float4 w4;
        w4.x = (vy0 & vx0) ? wy0 * wx0 * m : 0.f;
        w4.y = (vy0 & vx1) ? wy0 * wx1 * m : 0.f;
        w4.z = (vy1 & vx0) ? wy1 * wx0 * m : 0.f;
        w4.w = (vy1 & vx1) ? wy1 * wx1 * m : 0.f;
        const int y0c = min(max(y0, 0), HH - 1);
        const int y1c = min(max(y0 + 1, 0), HH - 1);
        const int x0c = min(max(x0, 0), WW - 1);
        const int x1c = min(max(x0 + 1, 0), WW - 1);
        ushort4 s4;
        s4.x = (unsigned short)(y0c * WW + x0c);
        s4.y = (unsigned short)(y0c * WW + x1c);
        s4.z = (unsigned short)(y1c * WW + x0c);
        s4.w = (unsigned short)(y1c * WW + x1c);
        const int idx = (b * 9 + k) * HW + p;
        g_w4[idx] = w4;
        g_idx[idx] = s4;
    }
}

// ============================================================================
// Kernel 2: bf16 split-precision tensor GEMM, K in k-major order.
// D += Ahi*Bhi + Ahi*Blo + Alo*Bhi.  CTA: 128 o x 128 px, BK=16.
// k is constant per chunk and changes every 8 chunks -> w4/idx cached in regs.
// Double-buffered smem + register prefetch (one sync per K-chunk).
// ============================================================================
#define BKC  16
#define BSTU 24                 // ushorts per tile row (48 B) -> conflict-free ldmatrix
#define NIT  (CKK / BKC)        // 72
#define STGU (128 * BSTU)       // ushorts per tile stage

__device__ __forceinline__ uint32_t smem_u32(const void* p) {
    uint32_t a;
    asm("{ .reg .u64 t; cvta.to.shared.u64 t, %1; cvt.u32.u64 %0, t; }" : "=r"(a) : "l"(p));
    return a;
}
__device__ __forceinline__ void ldm_x4(uint32_t* r, uint32_t addr) {
    asm volatile("ldmatrix.sync.aligned.m8n8.x4.shared.b16 {%0,%1,%2,%3}, [%4];"
                 : "=r"(r[0]), "=r"(r[1]), "=r"(r[2]), "=r"(r[3]) : "r"(addr));
}
__device__ __forceinline__ void mma_bf16(float* c, const uint32_t* a, uint32_t b0, uint32_t b1) {
    asm volatile("mma.sync.aligned.m16n8k16.row.col.f32.bf16.bf16.f32 "
                 "{%0,%1,%2,%3}, {%4,%5,%6,%7}, {%8,%9}, {%0,%1,%2,%3};"
                 : "+f"(c[0]), "+f"(c[1]), "+f"(c[2]), "+f"(c[3])
                 : "r"(a[0]), "r"(a[1]), "r"(a[2]), "r"(a[3]), "r"(b0), "r"(b1));
}

__global__ __launch_bounds__(256, 2)
void gemm_mma(const float* __restrict__ x, const float* __restrict__ bias,
              float* __restrict__ out) {
    __shared__ __align__(16) unsigned short Ahi[2][STGU];
    __shared__ __align__(16) unsigned short Alo[2][STGU];
    __shared__ __align__(16) unsigned short Bhi[2][STGU];
    __shared__ __align__(16) unsigned short Blo[2][STGU];

    const int tid = threadIdx.x;
    const int wid = tid >> 5;
    const int lid = tid & 31;
    const int n0 = blockIdx.x * 128;

    const int bimg = n0 >> 12;
    const int p0 = n0 & 4095;
    const int bimg9 = bimg * 9;
    const float* __restrict__ xb = x + (size_t)(bimg * CC) * HW;

    // producer coords
    const int arow = tid >> 1;          // A: 128 rows x 2 halves of 16 kk
    const int ahalf = tid & 1;
    const int px = tid & 127;           // B: 128 px x 2 halves of 16 kk (=16 c's)
    const int bh = tid >> 7;
    const int pj = p0 + px;

    // ldmatrix lane addresses (byte offsets within a tile)
    const int o0 = wid * 16;
    const uint32_t aOff =
        (uint32_t)((o0 + (lid & 7) + ((lid >> 3) & 1) * 8) * 48 + ((lid >> 4) & 1) * 16);
    const uint32_t bOff =
        (uint32_t)(((lid & 7) + ((lid >> 4) & 1) * 8) * 48 + ((lid >> 3) & 1) * 16);
    const uint32_t aHiS[2] = { smem_u32(Ahi[0]) + aOff, smem_u32(Ahi[1]) + aOff };
    const uint32_t aLoS[2] = { smem_u32(Alo[0]) + aOff, smem_u32(Alo[1]) + aOff };
    const uint32_t bHiS[2] = { smem_u32(Bhi[0]) + bOff, smem_u32(Bhi[1]) + bOff };
    const uint32_t bLoS[2] = { smem_u32(Blo[0]) + bOff, smem_u32(Blo[1]) + bOff };

    float acc[16][4];
#pragma unroll
    for (int i = 0; i < 16; ++i)
#pragma unroll
        for (int j = 0; j < 4; ++j) acc[i][j] = 0.f;

    // cached per-pixel bilinear state for the current k
    int kcur = -1;
    float4 cw4;
    ushort4 cidx;

    // ---- prefetch + store for chunk j into stage dst ----
    auto prefetch = [&](int j, uint4& pAh, uint4& pAl, uint4& pBh, uint4& pBl) {
        const int ck0 = j * BKC;
        const size_t gi = (size_t)arow * CKK + ck0 + ahalf * 8;
        pAh = *(const uint4*)(g_Wph + gi);
        pAl = *(const uint4*)(g_Wpl + gi);

        const int kn = j >> 3;                       // k for this chunk
        if (kn != kcur) {
            kcur = kn;
            const int t = (bimg9 + kn) * HW + pj;
            cw4 = __ldg(&g_w4[t]);
            cidx = __ldg(&g_idx[t]);
        }
        const int cbase = ((j & 7) * 16) + bh * 8;   // first channel of this half
        const float* __restrict__ xc = xb + (size_t)cbase * HW;
        unsigned short hu[8], lu[8];
#pragma unroll
        for (int j2 = 0; j2 < 8; ++j2) {
            const float v = cw4.x * __ldg(xc + cidx.x) + cw4.y * __ldg(xc + cidx.y)
                          + cw4.z * __ldg(xc + cidx.z) + cw4.w * __ldg(xc + cidx.w);
            const __nv_bfloat16 hb = __float2bfloat16(v);
            hu[j2] = __bfloat16_as_ushort(hb);
            lu[j2] = __bfloat16_as_ushort(__float2bfloat16(v - __bfloat162float(hb)));
            xc += HW;
        }
        pBh = make_uint4((uint32_t)hu[0] | ((uint32_t)hu[1] << 16),
                         (uint32_t)hu[2] | ((uint32_t)hu[3] << 16),
                         (uint32_t)hu[4] | ((uint32_t)hu[5] << 16),
                         (uint32_t)hu[6] | ((uint32_t)hu[7] << 16));
        pBl = make_uint4((uint32_t)lu[0] | ((uint32_t)lu[1] << 16),
                         (uint32_t)lu[2] | ((uint32_t)lu[3] << 16),
                         (uint32_t)lu[4] | ((uint32_t)lu[5] << 16),
                         (uint32_t)lu[6] | ((uint32_t)lu[7] << 16));
    };
    auto store_stage = [&](int dst, const uint4& pAh, const uint4& pAl,
                           const uint4& pBh, const uint4& pBl) {
        *(uint4*)(Ahi[dst] + arow * BSTU + ahalf * 8) = pAh;
        *(uint4*)(Alo[dst] + arow * BSTU + ahalf * 8) = pAl;
        *(uint4*)(Bhi[dst] + px * BSTU + bh * 8) = pBh;
        *(uint4*)(Blo[dst] + px * BSTU + bh * 8) = pBl;
    };

    // ---- prime stage 0 ----
    {
        uint4 a0, a1, b0, b1;
        prefetch(0, a0, a1, b0, b1);
        store_stage(0, a0, a1, b0, b1);
    }
    __syncthreads();

    int s = 0;
    for (int it = 0; it < NIT; ++it) {
        uint4 pAh, pAl, pBh, pBl;
        const bool has_next = (it + 1 < NIT);
        if (has_next) prefetch(it + 1, pAh, pAl, pBh, pBl);

        // ---- consume stage s ----
        uint32_t fAh[4], fAl[4];
        ldm_x4(fAh, aHiS[s]);
        ldm_x4(fAl, aLoS[s]);
#pragma unroll
        for (int pt = 0; pt < 8; ++pt) {
            uint32_t fBh[4], fBl[4];
            ldm_x4(fBh, bHiS[s] + pt * (16 * 48));
            ldm_x4(fBl, bLoS[s] + pt * (16 * 48));
            mma_bf16(acc[2 * pt], fAh, fBh[0], fBh[1]);
            mma_bf16(acc[2 * pt], fAh, fBl[0], fBl[1]);
            mma_bf16(acc[2 * pt], fAl, fBh[0], fBh[1]);
            mma_bf16(acc[2 * pt + 1], fAh, fBh[2], fBh[3]);
            mma_bf16(acc[2 * pt + 1], fAh, fBl[2], fBl[3]);
            mma_bf16(acc[2 * pt + 1], fAl, fBh[2], fBh[3]);
        }

        if (has_next) store_stage(s ^ 1, pAh, pAl, pBh, pBl);
        __syncthreads();
        s ^= 1;
    }

    // ---- epilogue: add bias, write out ----
    const int r = lid >> 2;
    const int q = lid & 3;
    const int oA = o0 + r;
    const int oB = o0 + r + 8;
    const float bvA = __ldg(bias + oA);
    const float bvB = __ldg(bias + oB);
    float* baseA = out + ((size_t)(bimg * OO + oA)) * HW + p0 + 2 * q;
    float* baseB = out + ((size_t)(bimg * OO + oB)) * HW + p0 + 2 * q;
#pragma unroll
    for (int nt = 0; nt < 16; ++nt) {
        float2 rA, rB;
        rA.x = acc[nt][0] + bvA; rA.y = acc[nt][1] + bvA;
        rB.x = acc[nt][2] + bvB; rB.y = acc[nt][3] + bvB;
        *(float2*)(baseA + nt * 8) = rA;
        *(float2*)(baseB + nt * 8) = rB;
    }
}

// ============================================================================
extern "C" void kernel_launch(void* const* d_in, const int* in_sizes, int n_in,
                              void* d_out, int out_size) {
    const float* x      = (const float*)d_in[0];   // (8,128,64,64)
    const float* w_om   = (const float*)d_in[1];   // (27,128,3,3)
    const float* b_om   = (const float*)d_in[2];   // (27,)
    const float* weight = (const float*)d_in[3];   // (128,128,3,3)
    const float* bias   = (const float*)d_in[4];   // (128,)
    float* out = (float*)d_out;                    // (8,128,64,64)

    prep_w<<<(OO * CKK + 255) / 256, 256>>>(weight);
    om_partial<<<dim3(NPIX / 256, NCH), 256>>>(x, w_om);
    om_final<<<NPIX / 256, 256>>>(b_om);
    gemm_mma<<<NPIX / 128, 256>>>(x, bias, out);
}

// round 9
// speedup vs baseline: 2.5828x; 1.3648x over previous
#include <cuda_runtime.h>
#include <cuda_bf16.h>
#include <cstdint>
#include <math.h>

#define BB   8
#define CC   128
#define OO   128
#define HH   64
#define WW   64
#define HW   4096
#define NPIX 32768
#define CKK  1152
#define NOM  27
#define OMM  32                // padded M for om GEMM

// ---------------- device scratch (allocation-free rule) ----------------
// k-major permuted main weights: Wp[o][k*128+c] = w[o][c*9+k], bf16 hi/lo
__device__ __align__(16) unsigned short g_Wph[OO * CKK];
__device__ __align__(16) unsigned short g_Wpl[OO * CKK];
// k-major permuted om weights (padded to 32 rows), bf16 hi/lo
__device__ __align__(16) unsigned short g_WomH[OMM * CKK];
__device__ __align__(16) unsigned short g_WomL[OMM * CKK];
__device__ float   g_om[NOM * NPIX];      // om conv result (fp32, pre-bias)
__device__ float4  g_w4[BB * 9 * HW];     // bilinear weights (mask+validity folded)
__device__ ushort4 g_idx[BB * 9 * HW];    // pre-clamped offsets in 64x64 plane

// ============================================================================
// common mma helpers
// ============================================================================
__device__ __forceinline__ uint32_t smem_u32(const void* p) {
    uint32_t a;
    asm("{ .reg .u64 t; cvta.to.shared.u64 t, %1; cvt.u32.u64 %0, t; }" : "=r"(a) : "l"(p));
    return a;
}
__device__ __forceinline__ void ldm_x4(uint32_t* r, uint32_t addr) {
    asm volatile("ldmatrix.sync.aligned.m8n8.x4.shared.b16 {%0,%1,%2,%3}, [%4];"
                 : "=r"(r[0]), "=r"(r[1]), "=r"(r[2]), "=r"(r[3]) : "r"(addr));
}
__device__ __forceinline__ void mma_bf16(float* c, const uint32_t* a, uint32_t b0, uint32_t b1) {
    asm volatile("mma.sync.aligned.m16n8k16.row.col.f32.bf16.bf16.f32 "
                 "{%0,%1,%2,%3}, {%4,%5,%6,%7}, {%8,%9}, {%0,%1,%2,%3};"
                 : "+f"(c[0]), "+f"(c[1]), "+f"(c[2]), "+f"(c[3])
                 : "r"(a[0]), "r"(a[1]), "r"(a[2]), "r"(a[3]), "r"(b0), "r"(b1));
}
__device__ __forceinline__ void bf16_split(float v, unsigned short& h, unsigned short& l) {
    const __nv_bfloat16 hb = __float2bfloat16(v);
    h = __bfloat16_as_ushort(hb);
    l = __bfloat16_as_ushort(__float2bfloat16(v - __bfloat162float(hb)));
}

// ============================================================================
// Kernel 0a: permute main weight to k-major, split bf16 hi/lo
// ============================================================================
__global__ __launch_bounds__(256)
void prep_w(const float* __restrict__ w) {
    const int i = blockIdx.x * 256 + threadIdx.x;
    if (i < OO * CKK) {
        const int o = i / CKK;
        const int kk = i - o * CKK;
        const int k = kk >> 7;
        const int c = kk & 127;
        unsigned short h, l;
        bf16_split(w[(size_t)o * CKK + c * 9 + k], h, l);
        g_Wph[i] = h; g_Wpl[i] = l;
    }
}

// ============================================================================
// Kernel 0b: permute om weight to k-major (pad rows 27..31 with 0), split hi/lo
// ============================================================================
__global__ __launch_bounds__(256)
void prep_wom(const float* __restrict__ w_om) {
    const int i = blockIdx.x * 256 + threadIdx.x;
    if (i < OMM * CKK) {
        const int o = i / CKK;
        const int kk = i - o * CKK;
        const int t = kk >> 7;
        const int c = kk & 127;
        const float v = (o < NOM) ? w_om[(size_t)o * CKK + c * 9 + t] : 0.f;
        unsigned short h, l;
        bf16_split(v, h, l);
        g_WomH[i] = h; g_WomL[i] = l;
    }
}

// ============================================================================
// Kernel 1a: om conv as bf16 split 3-term tensor GEMM.
// g_om[o][bp] = sum_kk Wom[o][kk] * X9[kk][bp], kk = t*128+c,
// X9[kk][bp] = x[c][p + shift(t)] with zero boundary.
// CTA: 32 o x 128 px; 8 warps = 2(m) x 4(n); 12 mma/warp/chunk.
// ============================================================================
#define BKC  16
#define BSTU 24                 // ushorts per tile row (48 B) -> conflict-free ldmatrix
#define NIT  (CKK / BKC)        // 72

__global__ __launch_bounds__(256)
void om_gemm(const float* __restrict__ x) {
    __shared__ __align__(16) unsigned short OAh[2][OMM * BSTU];
    __shared__ __align__(16) unsigned short OAl[2][OMM * BSTU];
    __shared__ __align__(16) unsigned short OBh[2][128 * BSTU];
    __shared__ __align__(16) unsigned short OBl[2][128 * BSTU];

    const int tid = threadIdx.x;
    const int wid = tid >> 5;
    const int lid = tid & 31;
    const int n0 = blockIdx.x * 128;

    const int bimg = n0 >> 12;
    const int p0 = n0 & 4095;
    const float* __restrict__ xbase = x + (size_t)(bimg * CC) * HW;

    // producers
    const int arow = tid >> 1;          // A: rows 0..31 (tid<64 active), 2 halves
    const int ahalf = tid & 1;
    const int px = tid & 127;           // B: 128 px x 2 halves of 16 c
    const int bh = tid >> 7;
    const int pj = p0 + px;
    const int y = pj >> 6;
    const int xx = pj & 63;

    // consumers: warp = 16 o x 32 px
    const int mid = wid >> 2;           // 0..1
    const int nq = wid & 3;             // 0..3
    const int m0 = mid * 16;
    const uint32_t aOff =
        (uint32_t)((m0 + (lid & 7) + ((lid >> 3) & 1) * 8) * 48 + ((lid >> 4) & 1) * 16);
    const uint32_t bOff =
        (uint32_t)(((lid & 7) + ((lid >> 4) & 1) * 8) * 48 + ((lid >> 3) & 1) * 16);
    const uint32_t aHiS[2] = { smem_u32(OAh[0]) + aOff, smem_u32(OAh[1]) + aOff };
    const uint32_t aLoS[2] = { smem_u32(OAl[0]) + aOff, smem_u32(OAl[1]) + aOff };
    const uint32_t bHiS[2] = { smem_u32(OBh[0]) + bOff, smem_u32(OBh[1]) + bOff };
    const uint32_t bLoS[2] = { smem_u32(OBl[0]) + bOff, smem_u32(OBl[1]) + bOff };

    float acc[4][4];
#pragma unroll
    for (int i = 0; i < 4; ++i)
#pragma unroll
        for (int j = 0; j < 4; ++j) acc[i][j] = 0.f;

    auto prefetch = [&](int j, uint4& pAh, uint4& pAl, uint4& pBh, uint4& pBl) {
        const int ck0 = j * BKC;
        if (tid < 64) {
            const size_t gi = (size_t)arow * CKK + ck0 + ahalf * 8;
            pAh = *(const uint4*)(g_WomH + gi);
            pAl = *(const uint4*)(g_WomL + gi);
        }
        const int t = j >> 3;
        const int dy = t / 3 - 1;
        const int dx = t - (t / 3) * 3 - 1;
        const int yy = y + dy;
        const int xxx = xx + dx;
        const bool ok = (yy >= 0) & (yy < HH) & (xxx >= 0) & (xxx < WW);
        const int off = ok ? yy * WW + xxx : 0;
        const int cbase = ((j & 7) * 16) + bh * 8;
        const float* __restrict__ xc = xbase + (size_t)cbase * HW + off;
        unsigned short hu[8], lu[8];
#pragma unroll
        for (int j2 = 0; j2 < 8; ++j2) {
            const float v = ok ? __ldg(xc) : 0.f;
            bf16_split(v, hu[j2], lu[j2]);
            xc += HW;
        }
        pBh = make_uint4((uint32_t)hu[0] | ((uint32_t)hu[1] << 16),
                         (uint32_t)hu[2] | ((uint32_t)hu[3] << 16),
                         (uint32_t)hu[4] | ((uint32_t)hu[5] << 16),
                         (uint32_t)hu[6] | ((uint32_t)hu[7] << 16));
        pBl = make_uint4((uint32_t)lu[0] | ((uint32_t)lu[1] << 16),
                         (uint32_t)lu[2] | ((uint32_t)lu[3] << 16),
                         (uint32_t)lu[4] | ((uint32_t)lu[5] << 16),
                         (uint32_t)lu[6] | ((uint32_t)lu[7] << 16));
    };
    auto store_stage = [&](int dst, const uint4& pAh, const uint4& pAl,
                           const uint4& pBh, const uint4& pBl) {
        if (tid < 64) {
            *(uint4*)(OAh[dst] + arow * BSTU + ahalf * 8) = pAh;
            *(uint4*)(OAl[dst] + arow * BSTU + ahalf * 8) = pAl;
        }
        *(uint4*)(OBh[dst] + px * BSTU + bh * 8) = pBh;
        *(uint4*)(OBl[dst] + px * BSTU + bh * 8) = pBl;
    };

    {
        uint4 a0, a1, b0, b1;
        prefetch(0, a0, a1, b0, b1);
        store_stage(0, a0, a1, b0, b1);
    }
    __syncthreads();

    int s = 0;
    for (int it = 0; it < NIT; ++it) {
        uint4 pAh, pAl, pBh, pBl;
        const bool has_next = (it + 1 < NIT);
        if (has_next) prefetch(it + 1, pAh, pAl, pBh, pBl);

        uint32_t fAh[4], fAl[4];
        ldm_x4(fAh, aHiS[s]);
        ldm_x4(fAl, aLoS[s]);
#pragma unroll
        for (int pt = 0; pt < 2; ++pt) {
            uint32_t fBh[4], fBl[4];
            const uint32_t boff = (uint32_t)((nq * 32 + pt * 16) * 48);
            ldm_x4(fBh, bHiS[s] + boff);
            ldm_x4(fBl, bLoS[s] + boff);
            mma_bf16(acc[2 * pt], fAh, fBh[0], fBh[1]);
            mma_bf16(acc[2 * pt], fAh, fBl[0], fBl[1]);
            mma_bf16(acc[2 * pt], fAl, fBh[0], fBh[1]);
            mma_bf16(acc[2 * pt + 1], fAh, fBh[2], fBh[3]);
            mma_bf16(acc[2 * pt + 1], fAh, fBl[2], fBl[3]);
            mma_bf16(acc[2 * pt + 1], fAl, fBh[2], fBh[3]);
        }

        if (has_next) store_stage(s ^ 1, pAh, pAl, pBh, pBl);
        __syncthreads();
        s ^= 1;
    }

    // epilogue: write fp32 rows o<27 to g_om
    const int r = lid >> 2;
    const int q = lid & 3;
    const int oA = m0 + r;
    const int oB = m0 + r + 8;
#pragma unroll
    for (int nt = 0; nt < 4; ++nt) {
        const int pxo = nq * 32 + (nt >> 1) * 16 + (nt & 1) * 8 + 2 * q;
        if (oA < NOM)
            *(float2*)(g_om + (size_t)oA * NPIX + n0 + pxo) = make_float2(acc[nt][0], acc[nt][1]);
        if (oB < NOM)
            *(float2*)(g_om + (size_t)oB * NPIX + n0 + pxo) = make_float2(acc[nt][2], acc[nt][3]);
    }
}

// ============================================================================
// Kernel 1b: add bias, softmax mask, emit bilinear weights + offsets
// ============================================================================
__global__ __launch_bounds__(256)
void om_final(const float* __restrict__ b_om) {
    const int bp = blockIdx.x * 256 + threadIdx.x;
    const int b = bp >> 12;
    const int p = bp & 4095;
    const int y = p >> 6;
    const int xx = p & 63;

    float acc[NOM];
#pragma unroll
    for (int oc = 0; oc < NOM; ++oc)
        acc[oc] = __ldg(b_om + oc) + g_om[(size_t)oc * NPIX + bp];

    float mx = acc[18];
#pragma unroll
    for (int k = 1; k < 9; ++k) mx = fmaxf(mx, acc[18 + k]);
    float e[9], s = 0.f;
#pragma unroll
    for (int k = 0; k < 9; ++k) { e[k] = expf(acc[18 + k] - mx); s += e[k]; }
    const float inv = 1.f / s;

#pragma unroll
    for (int k = 0; k < 9; ++k) {
        const float m = e[k] * inv;
        const float py = (float)(y - 1 + k / 3) + acc[2 * k];
        const float px = (float)(xx - 1 + k % 3) + acc[2 * k + 1];
        const float fy = floorf(py), fx = floorf(px);
        const int y0 = (int)fy, x0 = (int)fx;
        const float wy1 = py - fy, wx1 = px - fx;
        const float wy0 = 1.f - wy1, wx0 = 1.f - wx1;
        const bool vy0 = (y0 >= 0) & (y0 < HH);
        const bool vy1 = (y0 >= -1) & (y0 < HH - 1);
        const bool vx0 = (x0 >= 0) & (x0 < WW);
        const bool vx1 = (x0 >= -1) & (x0 < WW - 1);
        float4 w4;
        w4.x = (vy0 & vx0) ? wy0 * wx0 * m : 0.f;
        w4.y = (vy0 & vx1) ? wy0 * wx1 * m : 0.f;
        w4.z = (vy1 & vx0) ? wy1 * wx0 * m : 0.f;
        w4.w = (vy1 & vx1) ? wy1 * wx1 * m : 0.f;
        const int y0c = min(max(y0, 0), HH - 1);
        const int y1c = min(max(y0 + 1, 0), HH - 1);
        const int x0c = min(max(x0, 0), WW - 1);
        const int x1c = min(max(x0 + 1, 0), WW - 1);
        ushort4 s4;
        s4.x = (unsigned short)(y0c * WW + x0c);
        s4.y = (unsigned short)(y0c * WW + x1c);
        s4.z = (unsigned short)(y1c * WW + x0c);
        s4.w = (unsigned short)(y1c * WW + x1c);
        const int idx = (b * 9 + k) * HW + p;
        g_w4[idx] = w4;
        g_idx[idx] = s4;
    }
}

// ============================================================================
// Kernel 2: main bf16 split-precision tensor GEMM (unchanged from R8).
// ============================================================================
#define STGU (128 * BSTU)

__global__ __launch_bounds__(256, 2)
void gemm_mma(const float* __restrict__ x, const float* __restrict__ bias,
              float* __restrict__ out) {
    __shared__ __align__(16) unsigned short Ahi[2][STGU];
    __shared__ __align__(16) unsigned short Alo[2][STGU];
    __shared__ __align__(16) unsigned short Bhi[2][STGU];
    __shared__ __align__(16) unsigned short Blo[2][STGU];

    const int tid = threadIdx.x;
    const int wid = tid >> 5;
    const int lid = tid & 31;
    const int n0 = blockIdx.x * 128;

    const int bimg = n0 >> 12;
    const int p0 = n0 & 4095;
    const int bimg9 = bimg * 9;
    const float* __restrict__ xb = x + (size_t)(bimg * CC) * HW;

    const int arow = tid >> 1;
    const int ahalf = tid & 1;
    const int px = tid & 127;
    const int bh = tid >> 7;
    const int pj = p0 + px;

    const int o0 = wid * 16;
    const uint32_t aOff =
        (uint32_t)((o0 + (lid & 7) + ((lid >> 3) & 1) * 8) * 48 + ((lid >> 4) & 1) * 16);
    const uint32_t bOff =
        (uint32_t)(((lid & 7) + ((lid >> 4) & 1) * 8) * 48 + ((lid >> 3) & 1) * 16);
    const uint32_t aHiS[2] = { smem_u32(Ahi[0]) + aOff, smem_u32(Ahi[1]) + aOff };
    const uint32_t aLoS[2] = { smem_u32(Alo[0]) + aOff, smem_u32(Alo[1]) + aOff };
    const uint32_t bHiS[2] = { smem_u32(Bhi[0]) + bOff, smem_u32(Bhi[1]) + bOff };
    const uint32_t bLoS[2] = { smem_u32(Blo[0]) + bOff, smem_u32(Blo[1]) + bOff };

    float acc[16][4];
#pragma unroll
    for (int i = 0; i < 16; ++i)
#pragma unroll
        for (int j = 0; j < 4; ++j) acc[i][j] = 0.f;

    int kcur = -1;
    float4 cw4;
    ushort4 cidx;

    auto prefetch = [&](int j, uint4& pAh, uint4& pAl, uint4& pBh, uint4& pBl) {
        const int ck0 = j * BKC;
        const size_t gi = (size_t)arow * CKK + ck0 + ahalf * 8;
        pAh = *(const uint4*)(g_Wph + gi);
        pAl = *(const uint4*)(g_Wpl + gi);

        const int kn = j >> 3;
        if (kn != kcur) {
            kcur = kn;
            const int t = (bimg9 + kn) * HW + pj;
            cw4 = __ldg(&g_w4[t]);
            cidx = __ldg(&g_idx[t]);
        }
        const int cbase = ((j & 7) * 16) + bh * 8;
        const float* __restrict__ xc = xb + (size_t)cbase * HW;
        unsigned short hu[8], lu[8];
#pragma unroll
        for (int j2 = 0; j2 < 8; ++j2) {
            const float v = cw4.x * __ldg(xc + cidx.x) + cw4.y * __ldg(xc + cidx.y)
                          + cw4.z * __ldg(xc + cidx.z) + cw4.w * __ldg(xc + cidx.w);
            bf16_split(v, hu[j2], lu[j2]);
            xc += HW;
        }
        pBh = make_uint4((uint32_t)hu[0] | ((uint32_t)hu[1] << 16),
                         (uint32_t)hu[2] | ((uint32_t)hu[3] << 16),
                         (uint32_t)hu[4] | ((uint32_t)hu[5] << 16),
                         (uint32_t)hu[6] | ((uint32_t)hu[7] << 16));
        pBl = make_uint4((uint32_t)lu[0] | ((uint32_t)lu[1] << 16),
                         (uint32_t)lu[2] | ((uint32_t)lu[3] << 16),
                         (uint32_t)lu[4] | ((uint32_t)lu[5] << 16),
                         (uint32_t)lu[6] | ((uint32_t)lu[7] << 16));
    };
    auto store_stage = [&](int dst, const uint4& pAh, const uint4& pAl,
                           const uint4& pBh, const uint4& pBl) {
        *(uint4*)(Ahi[dst] + arow * BSTU + ahalf * 8) = pAh;
        *(uint4*)(Alo[dst] + arow * BSTU + ahalf * 8) = pAl;
        *(uint4*)(Bhi[dst] + px * BSTU + bh * 8) = pBh;
        *(uint4*)(Blo[dst] + px * BSTU + bh * 8) = pBl;
    };

    {
        uint4 a0, a1, b0, b1;
        prefetch(0, a0, a1, b0, b1);
        store_stage(0, a0, a1, b0, b1);
    }
    __syncthreads();

    int s = 0;
    for (int it = 0; it < NIT; ++it) {
        uint4 pAh, pAl, pBh, pBl;
        const bool has_next = (it + 1 < NIT);
        if (has_next) prefetch(it + 1, pAh, pAl, pBh, pBl);

        uint32_t fAh[4], fAl[4];
        ldm_x4(fAh, aHiS[s]);
        ldm_x4(fAl, aLoS[s]);
#pragma unroll
        for (int pt = 0; pt < 8; ++pt) {
            uint32_t fBh[4], fBl[4];
            ldm_x4(fBh, bHiS[s] + pt * (16 * 48));
            ldm_x4(fBl, bLoS[s] + pt * (16 * 48));
            mma_bf16(acc[2 * pt], fAh, fBh[0], fBh[1]);
            mma_bf16(acc[2 * pt], fAh, fBl[0], fBl[1]);
            mma_bf16(acc[2 * pt], fAl, fBh[0], fBh[1]);
            mma_bf16(acc[2 * pt + 1], fAh, fBh[2], fBh[3]);
            mma_bf16(acc[2 * pt + 1], fAh, fBl[2], fBl[3]);
            mma_bf16(acc[2 * pt + 1], fAl, fBh[2], fBh[3]);
        }

        if (has_next) store_stage(s ^ 1, pAh, pAl, pBh, pBl);
        __syncthreads();
        s ^= 1;
    }

    const int r = lid >> 2;
    const int q = lid & 3;
    const int oA = o0 + r;
    const int oB = o0 + r + 8;
    const float bvA = __ldg(bias + oA);
    const float bvB = __ldg(bias + oB);
    float* baseA = out + ((size_t)(bimg * OO + oA)) * HW + p0 + 2 * q;
    float* baseB = out + ((size_t)(bimg * OO + oB)) * HW + p0 + 2 * q;
#pragma unroll
    for (int nt = 0; nt < 16; ++nt) {
        float2 rA, rB;
        rA.x = acc[nt][0] + bvA; rA.y = acc[nt][1] + bvA;
        rB.x = acc[nt][2] + bvB; rB.y = acc[nt][3] + bvB;
        *(float2*)(baseA + nt * 8) = rA;
        *(float2*)(baseB + nt * 8) = rB;
    }
}

// ============================================================================
extern "C" void kernel_launch(void* const* d_in, const int* in_sizes, int n_in,
                              void* d_out, int out_size) {
    const float* x      = (const float*)d_in[0];   // (8,128,64,64)
    const float* w_om   = (const float*)d_in[1];   // (27,128,3,3)
    const float* b_om   = (const float*)d_in[2];   // (27,)
    const float* weight = (const float*)d_in[3];   // (128,128,3,3)
    const float* bias   = (const float*)d_in[4];   // (128,)
    float* out = (float*)d_out;                    // (8,128,64,64)

    prep_w<<<(OO * CKK + 255) / 256, 256>>>(weight);
    prep_wom<<<(OMM * CKK + 255) / 256, 256>>>(w_om);
    om_gemm<<<NPIX / 128, 256>>>(x);
    om_final<<<NPIX / 256, 256>>>(b_om);
    gemm_mma<<<NPIX / 128, 256>>>(x, bias, out);
}

// round 10
// speedup vs baseline: 2.5847x; 1.0007x over previous
#include <cuda_runtime.h>
#include <cuda_bf16.h>
#include <cstdint>
#include <math.h>

#define BB   8
#define CC   128
#define OO   128
#define HH   64
#define WW   64
#define HW   4096
#define NPIX 32768
#define CKK  1152
#define NOM  27
#define OMM  32                // padded M for om GEMM

// ---------------- device scratch (allocation-free rule) ----------------
// k-major permuted main weights: Wp[o][k*128+c] = w[o][c*9+k], bf16 hi/lo
__device__ __align__(16) unsigned short g_Wph[OO * CKK];
__device__ __align__(16) unsigned short g_Wpl[OO * CKK];
// k-major permuted om weights (padded to 32 rows), bf16 hi/lo
__device__ __align__(16) unsigned short g_WomH[OMM * CKK];
__device__ __align__(16) unsigned short g_WomL[OMM * CKK];
__device__ float   g_om[NOM * NPIX];      // om conv result (fp32, pre-bias)
__device__ float4  g_w4[BB * 9 * HW];     // bilinear weights (mask+validity folded)
__device__ ushort4 g_idx[BB * 9 * HW];    // pre-clamped offsets in 64x64 plane

// ============================================================================
// common mma helpers
// ============================================================================
__device__ __forceinline__ uint32_t smem_u32(const void* p) {
    uint32_t a;
    asm("{ .reg .u64 t; cvta.to.shared.u64 t, %1; cvt.u32.u64 %0, t; }" : "=r"(a) : "l"(p));
    return a;
}
__device__ __forceinline__ void ldm_x4(uint32_t* r, uint32_t addr) {
    asm volatile("ldmatrix.sync.aligned.m8n8.x4.shared.b16 {%0,%1,%2,%3}, [%4];"
                 : "=r"(r[0]), "=r"(r[1]), "=r"(r[2]), "=r"(r[3]) : "r"(addr));
}
__device__ __forceinline__ void mma_bf16(float* c, const uint32_t* a, uint32_t b0, uint32_t b1) {
    asm volatile("mma.sync.aligned.m16n8k16.row.col.f32.bf16.bf16.f32 "
                 "{%0,%1,%2,%3}, {%4,%5,%6,%7}, {%8,%9}, {%0,%1,%2,%3};"
                 : "+f"(c[0]), "+f"(c[1]), "+f"(c[2]), "+f"(c[3])
                 : "r"(a[0]), "r"(a[1]), "r"(a[2]), "r"(a[3]), "r"(b0), "r"(b1));
}
__device__ __forceinline__ void bf16_split(float v, unsigned short& h, unsigned short& l) {
    const __nv_bfloat16 hb = __float2bfloat16(v);
    h = __bfloat16_as_ushort(hb);
    l = __bfloat16_as_ushort(__float2bfloat16(v - __bfloat162float(hb)));
}

// ============================================================================
// Kernel 0a: permute main weight to k-major, split bf16 hi/lo
// ============================================================================
__global__ __launch_bounds__(256)
void prep_w(const float* __restrict__ w) {
    const int i = blockIdx.x * 256 + threadIdx.x;
    if (i < OO * CKK) {
        const int o = i / CKK;
        const int kk = i - o * CKK;
        const int k = kk >> 7;
        const int c = kk & 127;
        unsigned short h, l;
        bf16_split(w[(size_t)o * CKK + c * 9 + k], h, l);
        g_Wph[i] = h; g_Wpl[i] = l;
    }
}

// ============================================================================
// Kernel 0b: permute om weight to k-major (pad rows 27..31 with 0), split hi/lo
// ============================================================================
__global__ __launch_bounds__(256)
void prep_wom(const float* __restrict__ w_om) {
    const int i = blockIdx.x * 256 + threadIdx.x;
    if (i < OMM * CKK) {
        const int o = i / CKK;
        const int kk = i - o * CKK;
        const int t = kk >> 7;
        const int c = kk & 127;
        const float v = (o < NOM) ? w_om[(size_t)o * CKK + c * 9 + t] : 0.f;
        unsigned short h, l;
        bf16_split(v, h, l);
        g_WomH[i] = h; g_WomL[i] = l;
    }
}

// ============================================================================
// Kernel 1a: om conv as bf16 split 3-term tensor GEMM.
// g_om[o][bp] = sum_kk Wom[o][kk] * X9[kk][bp], kk = t*128+c,
// X9[kk][bp] = x[c][p + shift(t)] with zero boundary.
// CTA: 32 o x 128 px; 8 warps = 2(m) x 4(n); 12 mma/warp/chunk.
// ============================================================================
#define BKC  16
#define BSTU 24                 // ushorts per tile row (48 B) -> conflict-free ldmatrix
#define NIT  (CKK / BKC)        // 72

__global__ __launch_bounds__(256)
void om_gemm(const float* __restrict__ x) {
    __shared__ __align__(16) unsigned short OAh[2][OMM * BSTU];
    __shared__ __align__(16) unsigned short OAl[2][OMM * BSTU];
    __shared__ __align__(16) unsigned short OBh[2][128 * BSTU];
    __shared__ __align__(16) unsigned short OBl[2][128 * BSTU];

    const int tid = threadIdx.x;
    const int wid = tid >> 5;
    const int lid = tid & 31;
    const int n0 = blockIdx.x * 128;

    const int bimg = n0 >> 12;
    const int p0 = n0 & 4095;
    const float* __restrict__ xbase = x + (size_t)(bimg * CC) * HW;

    // producers
    const int arow = tid >> 1;          // A: rows 0..31 (tid<64 active), 2 halves
    const int ahalf = tid & 1;
    const int px = tid & 127;           // B: 128 px x 2 halves of 16 c
    const int bh = tid >> 7;
    const int pj = p0 + px;
    const int y = pj >> 6;
    const int xx = pj & 63;

    // consumers: warp = 16 o x 32 px
    const int mid = wid >> 2;           // 0..1
    const int nq = wid & 3;             // 0..3
    const int m0 = mid * 16;
    const uint32_t aOff =
        (uint32_t)((m0 + (lid & 7) + ((lid >> 3) & 1) * 8) * 48 + ((lid >> 4) & 1) * 16);
    const uint32_t bOff =
        (uint32_t)(((lid & 7) + ((lid >> 4) & 1) * 8) * 48 + ((lid >> 3) & 1) * 16);
    const uint32_t aHiS[2] = { smem_u32(OAh[0]) + aOff, smem_u32(OAh[1]) + aOff };
    const uint32_t aLoS[2] = { smem_u32(OAl[0]) + aOff, smem_u32(OAl[1]) + aOff };
    const uint32_t bHiS[2] = { smem_u32(OBh[0]) + bOff, smem_u32(OBh[1]) + bOff };
    const uint32_t bLoS[2] = { smem_u32(OBl[0]) + bOff, smem_u32(OBl[1]) + bOff };

    float acc[4][4];
#pragma unroll
    for (int i = 0; i < 4; ++i)
#pragma unroll
        for (int j = 0; j < 4; ++j) acc[i][j] = 0.f;

    auto prefetch = [&](int j, uint4& pAh, uint4& pAl, uint4& pBh, uint4& pBl) {
        const int ck0 = j * BKC;
        if (tid < 64) {
            const size_t gi = (size_t)arow * CKK + ck0 + ahalf * 8;
            pAh = *(const uint4*)(g_WomH + gi);
            pAl = *(const uint4*)(g_WomL + gi);
        }
        const int t = j >> 3;
        const int dy = t / 3 - 1;
        const int dx = t - (t / 3) * 3 - 1;
        const int yy = y + dy;
        const int xxx = xx + dx;
        const bool ok = (yy >= 0) & (yy < HH) & (xxx >= 0) & (xxx < WW);
        const int off = ok ? yy * WW + xxx : 0;
        const int cbase = ((j & 7) * 16) + bh * 8;
        const float* __restrict__ xc = xbase + (size_t)cbase * HW + off;
        unsigned short hu[8], lu[8];
#pragma unroll
        for (int j2 = 0; j2 < 8; ++j2) {
            const float v = ok ? __ldg(xc) : 0.f;
            bf16_split(v, hu[j2], lu[j2]);
            xc += HW;
        }
        pBh = make_uint4((uint32_t)hu[0] | ((uint32_t)hu[1] << 16),
                         (uint32_t)hu[2] | ((uint32_t)hu[3] << 16),
                         (uint32_t)hu[4] | ((uint32_t)hu[5] << 16),
                         (uint32_t)hu[6] | ((uint32_t)hu[7] << 16));
        pBl = make_uint4((uint32_t)lu[0] | ((uint32_t)lu[1] << 16),
                         (uint32_t)lu[2] | ((uint32_t)lu[3] << 16),
                         (uint32_t)lu[4] | ((uint32_t)lu[5] << 16),
                         (uint32_t)lu[6] | ((uint32_t)lu[7] << 16));
    };
    auto store_stage = [&](int dst, const uint4& pAh, const uint4& pAl,
                           const uint4& pBh, const uint4& pBl) {
        if (tid < 64) {
            *(uint4*)(OAh[dst] + arow * BSTU + ahalf * 8) = pAh;
            *(uint4*)(OAl[dst] + arow * BSTU + ahalf * 8) = pAl;
        }
        *(uint4*)(OBh[dst] + px * BSTU + bh * 8) = pBh;
        *(uint4*)(OBl[dst] + px * BSTU + bh * 8) = pBl;
    };

    {
        uint4 a0, a1, b0, b1;
        prefetch(0, a0, a1, b0, b1);
        store_stage(0, a0, a1, b0, b1);
    }
    __syncthreads();

    int s = 0;
    for (int it = 0; it < NIT; ++it) {
        uint4 pAh, pAl, pBh, pBl;
        const bool has_next = (it + 1 < NIT);
        if (has_next) prefetch(it + 1, pAh, pAl, pBh, pBl);

        uint32_t fAh[4], fAl[4];
        ldm_x4(fAh, aHiS[s]);
        ldm_x4(fAl, aLoS[s]);
#pragma unroll
        for (int pt = 0; pt < 2; ++pt) {
            uint32_t fBh[4], fBl[4];
            const uint32_t boff = (uint32_t)((nq * 32 + pt * 16) * 48);
            ldm_x4(fBh, bHiS[s] + boff);
            ldm_x4(fBl, bLoS[s] + boff);
            mma_bf16(acc[2 * pt], fAh, fBh[0], fBh[1]);
            mma_bf16(acc[2 * pt], fAh, fBl[0], fBl[1]);
            mma_bf16(acc[2 * pt], fAl, fBh[0], fBh[1]);
            mma_bf16(acc[2 * pt + 1], fAh, fBh[2], fBh[3]);
            mma_bf16(acc[2 * pt + 1], fAh, fBl[2], fBl[3]);
            mma_bf16(acc[2 * pt + 1], fAl, fBh[2], fBh[3]);
        }

        if (has_next) store_stage(s ^ 1, pAh, pAl, pBh, pBl);
        __syncthreads();
        s ^= 1;
    }

    // epilogue: write fp32 rows o<27 to g_om
    const int r = lid >> 2;
    const int q = lid & 3;
    const int oA = m0 + r;
    const int oB = m0 + r + 8;
#pragma unroll
    for (int nt = 0; nt < 4; ++nt) {
        const int pxo = nq * 32 + (nt >> 1) * 16 + (nt & 1) * 8 + 2 * q;
        if (oA < NOM)
            *(float2*)(g_om + (size_t)oA * NPIX + n0 + pxo) = make_float2(acc[nt][0], acc[nt][1]);
        if (oB < NOM)
            *(float2*)(g_om + (size_t)oB * NPIX + n0 + pxo) = make_float2(acc[nt][2], acc[nt][3]);
    }
}

// ============================================================================
// Kernel 1b: add bias, softmax mask, emit bilinear weights + offsets
// ============================================================================
__global__ __launch_bounds__(256)
void om_final(const float* __restrict__ b_om) {
    const int bp = blockIdx.x * 256 + threadIdx.x;
    const int b = bp >> 12;
    const int p = bp & 4095;
    const int y = p >> 6;
    const int xx = p & 63;

    float acc[NOM];
#pragma unroll
    for (int oc = 0; oc < NOM; ++oc)
        acc[oc] = __ldg(b_om + oc) + g_om[(size_t)oc * NPIX + bp];

    float mx = acc[18];
#pragma unroll
    for (int k = 1; k < 9; ++k) mx = fmaxf(mx, acc[18 + k]);
    float e[9], s = 0.f;
#pragma unroll
    for (int k = 0; k < 9; ++k) { e[k] = expf(acc[18 + k] - mx); s += e[k]; }
    const float inv = 1.f / s;

#pragma unroll
    for (int k = 0; k < 9; ++k) {
        const float m = e[k] * inv;
        const float py = (float)(y - 1 + k / 3) + acc[2 * k];
        const float px = (float)(xx - 1 + k % 3) + acc[2 * k + 1];
        const float fy = floorf(py), fx = floorf(px);
        const int y0 = (int)fy, x0 = (int)fx;
        const float wy1 = py - fy, wx1 = px - fx;
        const float wy0 = 1.f - wy1, wx0 = 1.f - wx1;
        const bool vy0 = (y0 >= 0) & (y0 < HH);
        const bool vy1 = (y0 >= -1) & (y0 < HH - 1);
        const bool vx0 = (x0 >= 0) & (x0 < WW);
        const bool vx1 = (x0 >= -1) & (x0 < WW - 1);
        float4 w4;
        w4.x = (vy0 & vx0) ? wy0 * wx0 * m : 0.f;
        w4.y = (vy0 & vx1) ? wy0 * wx1 * m : 0.f;
        w4.z = (vy1 & vx0) ? wy1 * wx0 * m : 0.f;
        w4.w = (vy1 & vx1) ? wy1 * wx1 * m : 0.f;
        const int y0c = min(max(y0, 0), HH - 1);
        const int y1c = min(max(y0 + 1, 0), HH - 1);
        const int x0c = min(max(x0, 0), WW - 1);
        const int x1c = min(max(x0 + 1, 0), WW - 1);
        ushort4 s4;
        s4.x = (unsigned short)(y0c * WW + x0c);
        s4.y = (unsigned short)(y0c * WW + x1c);
        s4.z = (unsigned short)(y1c * WW + x0c);
        s4.w = (unsigned short)(y1c * WW + x1c);
        const int idx = (b * 9 + k) * HW + p;
        g_w4[idx] = w4;
        g_idx[idx] = s4;
    }
}

// ============================================================================
// Kernel 2: main bf16 split-precision tensor GEMM (unchanged from R8).
// ============================================================================
#define STGU (128 * BSTU)

__global__ __launch_bounds__(256, 2)
void gemm_mma(const float* __restrict__ x, const float* __restrict__ bias,
              float* __restrict__ out) {
    __shared__ __align__(16) unsigned short Ahi[2][STGU];
    __shared__ __align__(16) unsigned short Alo[2][STGU];
    __shared__ __align__(16) unsigned short Bhi[2][STGU];
    __shared__ __align__(16) unsigned short Blo[2][STGU];

    const int tid = threadIdx.x;
    const int wid = tid >> 5;
    const int lid = tid & 31;
    const int n0 = blockIdx.x * 128;

    const int bimg = n0 >> 12;
    const int p0 = n0 & 4095;
    const int bimg9 = bimg * 9;
    const float* __restrict__ xb = x + (size_t)(bimg * CC) * HW;

    const int arow = tid >> 1;
    const int ahalf = tid & 1;
    const int px = tid & 127;
    const int bh = tid >> 7;
    const int pj = p0 + px;

    const int o0 = wid * 16;
    const uint32_t aOff =
        (uint32_t)((o0 + (lid & 7) + ((lid >> 3) & 1) * 8) * 48 + ((lid >> 4) & 1) * 16);
    const uint32_t bOff =
        (uint32_t)(((lid & 7) + ((lid >> 4) & 1) * 8) * 48 + ((lid >> 3) & 1) * 16);
    const uint32_t aHiS[2] = { smem_u32(Ahi[0]) + aOff, smem_u32(Ahi[1]) + aOff };
    const uint32_t aLoS[2] = { smem_u32(Alo[0]) + aOff, smem_u32(Alo[1]) + aOff };
    const uint32_t bHiS[2] = { smem_u32(Bhi[0]) + bOff, smem_u32(Bhi[1]) + bOff };
    const uint32_t bLoS[2] = { smem_u32(Blo[0]) + bOff, smem_u32(Blo[1]) + bOff };

    float acc[16][4];
#pragma unroll
    for (int i = 0; i < 16; ++i)
#pragma unroll
        for (int j = 0; j < 4; ++j) acc[i][j] = 0.f;

    int kcur = -1;
    float4 cw4;
    ushort4 cidx;

    auto prefetch = [&](int j, uint4& pAh, uint4& pAl, uint4& pBh, uint4& pBl) {
        const int ck0 = j * BKC;
        const size_t gi = (size_t)arow * CKK + ck0 + ahalf * 8;
        pAh = *(const uint4*)(g_Wph + gi);
        pAl = *(const uint4*)(g_Wpl + gi);

        const int kn = j >> 3;
        if (kn != kcur) {
            kcur = kn;
            const int t = (bimg9 + kn) * HW + pj;
            cw4 = __ldg(&g_w4[t]);
            cidx = __ldg(&g_idx[t]);
        }
        const int cbase = ((j & 7) * 16) + bh * 8;
        const float* __restrict__ xc = xb + (size_t)cbase * HW;
        unsigned short hu[8], lu[8];
#pragma unroll
        for (int j2 = 0; j2 < 8; ++j2) {
            const float v = cw4.x * __ldg(xc + cidx.x) + cw4.y * __ldg(xc + cidx.y)
                          + cw4.z * __ldg(xc + cidx.z) + cw4.w * __ldg(xc + cidx.w);
            bf16_split(v, hu[j2], lu[j2]);
            xc += HW;
        }
        pBh = make_uint4((uint32_t)hu[0] | ((uint32_t)hu[1] << 16),
                         (uint32_t)hu[2] | ((uint32_t)hu[3] << 16),
                         (uint32_t)hu[4] | ((uint32_t)hu[5] << 16),
                         (uint32_t)hu[6] | ((uint32_t)hu[7] << 16));
        pBl = make_uint4((uint32_t)lu[0] | ((uint32_t)lu[1] << 16),
                         (uint32_t)lu[2] | ((uint32_t)lu[3] << 16),
                         (uint32_t)lu[4] | ((uint32_t)lu[5] << 16),
                         (uint32_t)lu[6] | ((uint32_t)lu[7] << 16));
    };
    auto store_stage = [&](int dst, const uint4& pAh, const uint4& pAl,
                           const uint4& pBh, const uint4& pBl) {
        *(uint4*)(Ahi[dst] + arow * BSTU + ahalf * 8) = pAh;
        *(uint4*)(Alo[dst] + arow * BSTU + ahalf * 8) = pAl;
        *(uint4*)(Bhi[dst] + px * BSTU + bh * 8) = pBh;
        *(uint4*)(Blo[dst] + px * BSTU + bh * 8) = pBl;
    };

    {
        uint4 a0, a1, b0, b1;
        prefetch(0, a0, a1, b0, b1);
        store_stage(0, a0, a1, b0, b1);
    }
    __syncthreads();

    int s = 0;
    for (int it = 0; it < NIT; ++it) {
        uint4 pAh, pAl, pBh, pBl;
        const bool has_next = (it + 1 < NIT);
        if (has_next) prefetch(it + 1, pAh, pAl, pBh, pBl);

        uint32_t fAh[4], fAl[4];
        ldm_x4(fAh, aHiS[s]);
        ldm_x4(fAl, aLoS[s]);
#pragma unroll
        for (int pt = 0; pt < 8; ++pt) {
            uint32_t fBh[4], fBl[4];
            ldm_x4(fBh, bHiS[s] + pt * (16 * 48));
            ldm_x4(fBl, bLoS[s] + pt * (16 * 48));
            mma_bf16(acc[2 * pt], fAh, fBh[0], fBh[1]);
            mma_bf16(acc[2 * pt], fAh, fBl[0], fBl[1]);
            mma_bf16(acc[2 * pt], fAl, fBh[0], fBh[1]);
            mma_bf16(acc[2 * pt + 1], fAh, fBh[2], fBh[3]);
            mma_bf16(acc[2 * pt + 1], fAh, fBl[2], fBl[3]);
            mma_bf16(acc[2 * pt + 1], fAl, fBh[2], fBh[3]);
        }

        if (has_next) store_stage(s ^ 1, pAh, pAl, pBh, pBl);
        __syncthreads();
        s ^= 1;
    }

    const int r = lid >> 2;
    const int q = lid & 3;
    const int oA = o0 + r;
    const int oB = o0 + r + 8;
    const float bvA = __ldg(bias + oA);
    const float bvB = __ldg(bias + oB);
    float* baseA = out + ((size_t)(bimg * OO + oA)) * HW + p0 + 2 * q;
    float* baseB = out + ((size_t)(bimg * OO + oB)) * HW + p0 + 2 * q;
#pragma unroll
    for (int nt = 0; nt < 16; ++nt) {
        float2 rA, rB;
        rA.x = acc[nt][0] + bvA; rA.y = acc[nt][1] + bvA;
        rB.x = acc[nt][2] + bvB; rB.y = acc[nt][3] + bvB;
        *(float2*)(baseA + nt * 8) = rA;
        *(float2*)(baseB + nt * 8) = rB;
    }
}

// ============================================================================
extern "C" void kernel_launch(void* const* d_in, const int* in_sizes, int n_in,
                              void* d_out, int out_size) {
    const float* x      = (const float*)d_in[0];   // (8,128,64,64)
    const float* w_om   = (const float*)d_in[1];   // (27,128,3,3)
    const float* b_om   = (const float*)d_in[2];   // (27,)
    const float* weight = (const float*)d_in[3];   // (128,128,3,3)
    const float* bias   = (const float*)d_in[4];   // (128,)
    float* out = (float*)d_out;                    // (8,128,64,64)

    prep_w<<<(OO * CKK + 255) / 256, 256>>>(weight);
    prep_wom<<<(OMM * CKK + 255) / 256, 256>>>(w_om);
    om_gemm<<<NPIX / 128, 256>>>(x);
    om_final<<<NPIX / 256, 256>>>(b_om);
    gemm_mma<<<NPIX / 128, 256>>>(x, bias, out);
}

// round 11
// speedup vs baseline: 2.6092x; 1.0095x over previous
#include <cuda_runtime.h>
#include <cuda_bf16.h>
#include <cstdint>
#include <math.h>

#define BB   8
#define CC   128
#define OO   128
#define HH   64
#define WW   64
#define HW   4096
#define NPIX 32768
#define CKK  1152
#define NOM  27
#define OMM  32                // padded M for om GEMM

// ---------------- device scratch (allocation-free rule) ----------------
// k-major permuted main weights: Wp[o][k*128+c] = w[o][c*9+k], bf16 hi/lo
__device__ __align__(16) unsigned short g_Wph[OO * CKK];
__device__ __align__(16) unsigned short g_Wpl[OO * CKK];
// k-major permuted om weights (padded to 32 rows), bf16 hi/lo
__device__ __align__(16) unsigned short g_WomH[OMM * CKK];
__device__ __align__(16) unsigned short g_WomL[OMM * CKK];
__device__ float   g_om[NOM * NPIX];      // om conv result (fp32, pre-bias)
__device__ float4  g_w4[BB * 9 * HW];     // bilinear weights (mask+validity folded)
__device__ ushort4 g_idx[BB * 9 * HW];    // pre-clamped offsets in 64x64 plane

// ============================================================================
// common mma helpers
// ============================================================================
__device__ __forceinline__ uint32_t smem_u32(const void* p) {
    uint32_t a;
    asm("{ .reg .u64 t; cvta.to.shared.u64 t, %1; cvt.u32.u64 %0, t; }" : "=r"(a) : "l"(p));
    return a;
}
__device__ __forceinline__ void ldm_x4(uint32_t* r, uint32_t addr) {
    asm volatile("ldmatrix.sync.aligned.m8n8.x4.shared.b16 {%0,%1,%2,%3}, [%4];"
                 : "=r"(r[0]), "=r"(r[1]), "=r"(r[2]), "=r"(r[3]) : "r"(addr));
}
__device__ __forceinline__ void mma_bf16(float* c, const uint32_t* a, uint32_t b0, uint32_t b1) {
    asm volatile("mma.sync.aligned.m16n8k16.row.col.f32.bf16.bf16.f32 "
                 "{%0,%1,%2,%3}, {%4,%5,%6,%7}, {%8,%9}, {%0,%1,%2,%3};"
                 : "+f"(c[0]), "+f"(c[1]), "+f"(c[2]), "+f"(c[3])
                 : "r"(a[0]), "r"(a[1]), "r"(a[2]), "r"(a[3]), "r"(b0), "r"(b1));
}
__device__ __forceinline__ void bf16_split(float v, unsigned short& h, unsigned short& l) {
    const __nv_bfloat16 hb = __float2bfloat16(v);
    h = __bfloat16_as_ushort(hb);
    l = __bfloat16_as_ushort(__float2bfloat16(v - __bfloat162float(hb)));
}

// ============================================================================
// Kernel 0a: permute main weight to k-major, split bf16 hi/lo
// ============================================================================
__global__ __launch_bounds__(256)
void prep_w(const float* __restrict__ w) {
    const int i = blockIdx.x * 256 + threadIdx.x;
    if (i < OO * CKK) {
        const int o = i / CKK;
        const int kk = i - o * CKK;
        const int k = kk >> 7;
        const int c = kk & 127;
        unsigned short h, l;
        bf16_split(w[(size_t)o * CKK + c * 9 + k], h, l);
        g_Wph[i] = h; g_Wpl[i] = l;
    }
}

// ============================================================================
// Kernel 0b: permute om weight to k-major (pad rows 27..31 with 0), split hi/lo
// ============================================================================
__global__ __launch_bounds__(256)
void prep_wom(const float* __restrict__ w_om) {
    const int i = blockIdx.x * 256 + threadIdx.x;
    if (i < OMM * CKK) {
        const int o = i / CKK;
        const int kk = i - o * CKK;
        const int t = kk >> 7;
        const int c = kk & 127;
        const float v = (o < NOM) ? w_om[(size_t)o * CKK + c * 9 + t] : 0.f;
        unsigned short h, l;
        bf16_split(v, h, l);
        g_WomH[i] = h; g_WomL[i] = l;
    }
}

// ============================================================================
// Kernel 1a: om conv as bf16 split 3-term tensor GEMM (unchanged from R10).
// ============================================================================
#define BKC  16
#define BSTU 24                 // ushorts per tile row (48 B) -> conflict-free ldmatrix
#define NIT  (CKK / BKC)        // 72

__global__ __launch_bounds__(256)
void om_gemm(const float* __restrict__ x) {
    __shared__ __align__(16) unsigned short OAh[2][OMM * BSTU];
    __shared__ __align__(16) unsigned short OAl[2][OMM * BSTU];
    __shared__ __align__(16) unsigned short OBh[2][128 * BSTU];
    __shared__ __align__(16) unsigned short OBl[2][128 * BSTU];

    const int tid = threadIdx.x;
    const int wid = tid >> 5;
    const int lid = tid & 31;
    const int n0 = blockIdx.x * 128;

    const int bimg = n0 >> 12;
    const int p0 = n0 & 4095;
    const float* __restrict__ xbase = x + (size_t)(bimg * CC) * HW;

    const int arow = tid >> 1;
    const int ahalf = tid & 1;
    const int px = tid & 127;
    const int bh = tid >> 7;
    const int pj = p0 + px;
    const int y = pj >> 6;
    const int xx = pj & 63;

    const int mid = wid >> 2;
    const int nq = wid & 3;
    const int m0 = mid * 16;
    const uint32_t aOff =
        (uint32_t)((m0 + (lid & 7) + ((lid >> 3) & 1) * 8) * 48 + ((lid >> 4) & 1) * 16);
    const uint32_t bOff =
        (uint32_t)(((lid & 7) + ((lid >> 4) & 1) * 8) * 48 + ((lid >> 3) & 1) * 16);
    const uint32_t aHiS[2] = { smem_u32(OAh[0]) + aOff, smem_u32(OAh[1]) + aOff };
    const uint32_t aLoS[2] = { smem_u32(OAl[0]) + aOff, smem_u32(OAl[1]) + aOff };
    const uint32_t bHiS[2] = { smem_u32(OBh[0]) + bOff, smem_u32(OBh[1]) + bOff };
    const uint32_t bLoS[2] = { smem_u32(OBl[0]) + bOff, smem_u32(OBl[1]) + bOff };

    float acc[4][4];
#pragma unroll
    for (int i = 0; i < 4; ++i)
#pragma unroll
        for (int j = 0; j < 4; ++j) acc[i][j] = 0.f;

    auto prefetch = [&](int j, uint4& pAh, uint4& pAl, uint4& pBh, uint4& pBl) {
        const int ck0 = j * BKC;
        if (tid < 64) {
            const size_t gi = (size_t)arow * CKK + ck0 + ahalf * 8;
            pAh = *(const uint4*)(g_WomH + gi);
            pAl = *(const uint4*)(g_WomL + gi);
        }
        const int t = j >> 3;
        const int dy = t / 3 - 1;
        const int dx = t - (t / 3) * 3 - 1;
        const int yy = y + dy;
        const int xxx = xx + dx;
        const bool ok = (yy >= 0) & (yy < HH) & (xxx >= 0) & (xxx < WW);
        const int off = ok ? yy * WW + xxx : 0;
        const int cbase = ((j & 7) * 16) + bh * 8;
        const float* __restrict__ xc = xbase + (size_t)cbase * HW + off;
        unsigned short hu[8], lu[8];
#pragma unroll
        for (int j2 = 0; j2 < 8; ++j2) {
            const float v = ok ? __ldg(xc) : 0.f;
            bf16_split(v, hu[j2], lu[j2]);
            xc += HW;
        }
        pBh = make_uint4((uint32_t)hu[0] | ((uint32_t)hu[1] << 16),
                         (uint32_t)hu[2] | ((uint32_t)hu[3] << 16),
                         (uint32_t)hu[4] | ((uint32_t)hu[5] << 16),
                         (uint32_t)hu[6] | ((uint32_t)hu[7] << 16));
        pBl = make_uint4((uint32_t)lu[0] | ((uint32_t)lu[1] << 16),
                         (uint32_t)lu[2] | ((uint32_t)lu[3] << 16),
                         (uint32_t)lu[4] | ((uint32_t)lu[5] << 16),
                         (uint32_t)lu[6] | ((uint32_t)lu[7] << 16));
    };
    auto store_stage = [&](int dst, const uint4& pAh, const uint4& pAl,
                           const uint4& pBh, const uint4& pBl) {
        if (tid < 64) {
            *(uint4*)(OAh[dst] + arow * BSTU + ahalf * 8) = pAh;
            *(uint4*)(OAl[dst] + arow * BSTU + ahalf * 8) = pAl;
        }
        *(uint4*)(OBh[dst] + px * BSTU + bh * 8) = pBh;
        *(uint4*)(OBl[dst] + px * BSTU + bh * 8) = pBl;
    };

    {
        uint4 a0, a1, b0, b1;
        prefetch(0, a0, a1, b0, b1);
        store_stage(0, a0, a1, b0, b1);
    }
    __syncthreads();

    int s = 0;
    for (int it = 0; it < NIT; ++it) {
        uint4 pAh, pAl, pBh, pBl;
        const bool has_next = (it + 1 < NIT);
        if (has_next) prefetch(it + 1, pAh, pAl, pBh, pBl);

        uint32_t fAh[4], fAl[4];
        ldm_x4(fAh, aHiS[s]);
        ldm_x4(fAl, aLoS[s]);
#pragma unroll
        for (int pt = 0; pt < 2; ++pt) {
            uint32_t fBh[4], fBl[4];
            const uint32_t boff = (uint32_t)((nq * 32 + pt * 16) * 48);
            ldm_x4(fBh, bHiS[s] + boff);
            ldm_x4(fBl, bLoS[s] + boff);
            mma_bf16(acc[2 * pt], fAh, fBh[0], fBh[1]);
            mma_bf16(acc[2 * pt], fAh, fBl[0], fBl[1]);
            mma_bf16(acc[2 * pt], fAl, fBh[0], fBh[1]);
            mma_bf16(acc[2 * pt + 1], fAh, fBh[2], fBh[3]);
            mma_bf16(acc[2 * pt + 1], fAh, fBl[2], fBl[3]);
            mma_bf16(acc[2 * pt + 1], fAl, fBh[2], fBh[3]);
        }

        if (has_next) store_stage(s ^ 1, pAh, pAl, pBh, pBl);
        __syncthreads();
        s ^= 1;
    }

    const int r = lid >> 2;
    const int q = lid & 3;
    const int oA = m0 + r;
    const int oB = m0 + r + 8;
#pragma unroll
    for (int nt = 0; nt < 4; ++nt) {
        const int pxo = nq * 32 + (nt >> 1) * 16 + (nt & 1) * 8 + 2 * q;
        if (oA < NOM)
            *(float2*)(g_om + (size_t)oA * NPIX + n0 + pxo) = make_float2(acc[nt][0], acc[nt][1]);
        if (oB < NOM)
            *(float2*)(g_om + (size_t)oB * NPIX + n0 + pxo) = make_float2(acc[nt][2], acc[nt][3]);
    }
}

// ============================================================================
// Kernel 1b: add bias, softmax mask, emit bilinear weights + offsets
// ============================================================================
__global__ __launch_bounds__(256)
void om_final(const float* __restrict__ b_om) {
    const int bp = blockIdx.x * 256 + threadIdx.x;
    const int b = bp >> 12;
    const int p = bp & 4095;
    const int y = p >> 6;
    const int xx = p & 63;

    float acc[NOM];
#pragma unroll
    for (int oc = 0; oc < NOM; ++oc)
        acc[oc] = __ldg(b_om + oc) + g_om[(size_t)oc * NPIX + bp];

    float mx = acc[18];
#pragma unroll
    for (int k = 1; k < 9; ++k) mx = fmaxf(mx, acc[18 + k]);
    float e[9], s = 0.f;
#pragma unroll
    for (int k = 0; k < 9; ++k) { e[k] = expf(acc[18 + k] - mx); s += e[k]; }
    const float inv = 1.f / s;

#pragma unroll
    for (int k = 0; k < 9; ++k) {
        const float m = e[k] * inv;
        const float py = (float)(y - 1 + k / 3) + acc[2 * k];
        const float px = (float)(xx - 1 + k % 3) + acc[2 * k + 1];
        const float fy = floorf(py), fx = floorf(px);
        const int y0 = (int)fy, x0 = (int)fx;
        const float wy1 = py - fy, wx1 = px - fx;
        const float wy0 = 1.f - wy1, wx0 = 1.f - wx1;
        const bool vy0 = (y0 >= 0) & (y0 < HH);
        const bool vy1 = (y0 >= -1) & (y0 < HH - 1);
        const bool vx0 = (x0 >= 0) & (x0 < WW);
        const bool vx1 = (x0 >= -1) & (x0 < WW - 1);
        float4 w4;
        w4.x = (vy0 & vx0) ? wy0 * wx0 * m : 0.f;
        w4.y = (vy0 & vx1) ? wy0 * wx1 * m : 0.f;
        w4.z = (vy1 & vx0) ? wy1 * wx0 * m : 0.f;
        w4.w = (vy1 & vx1) ? wy1 * wx1 * m : 0.f;
        const int y0c = min(max(y0, 0), HH - 1);
        const int y1c = min(max(y0 + 1, 0), HH - 1);
        const int x0c = min(max(x0, 0), WW - 1);
        const int x1c = min(max(x0 + 1, 0), WW - 1);
        ushort4 s4;
        s4.x = (unsigned short)(y0c * WW + x0c);
        s4.y = (unsigned short)(y0c * WW + x1c);
        s4.z = (unsigned short)(y1c * WW + x0c);
        s4.w = (unsigned short)(y1c * WW + x1c);
        const int idx = (b * 9 + k) * HW + p;
        g_w4[idx] = w4;
        g_idx[idx] = s4;
    }
}

// ============================================================================
// Kernel 2: main bf16 split-precision tensor GEMM.
// NEW: 4(m) x 2(n) warp grid — each warp 32o x 64px. Halves B smem re-reads,
// ldm per warp-chunk 18 -> 12. MMA count/acc regs unchanged.
// ============================================================================
#define STGU (128 * BSTU)

__global__ __launch_bounds__(256, 2)
void gemm_mma(const float* __restrict__ x, const float* __restrict__ bias,
              float* __restrict__ out) {
    __shared__ __align__(16) unsigned short Ahi[2][STGU];
    __shared__ __align__(16) unsigned short Alo[2][STGU];
    __shared__ __align__(16) unsigned short Bhi[2][STGU];
    __shared__ __align__(16) unsigned short Blo[2][STGU];

    const int tid = threadIdx.x;
    const int wid = tid >> 5;
    const int lid = tid & 31;
    const int n0 = blockIdx.x * 128;

    const int bimg = n0 >> 12;
    const int p0 = n0 & 4095;
    const int bimg9 = bimg * 9;
    const float* __restrict__ xb = x + (size_t)(bimg * CC) * HW;

    const int arow = tid >> 1;
    const int ahalf = tid & 1;
    const int px = tid & 127;
    const int bh = tid >> 7;
    const int pj = p0 + px;

    // 4x2 warp grid: warp covers o rows [m0, m0+32), px cols [nq*64, nq*64+64)
    const int mid = wid >> 1;           // 0..3
    const int nq = wid & 1;             // 0..1
    const int m0 = mid * 32;
    const uint32_t aOff =
        (uint32_t)((m0 + (lid & 7) + ((lid >> 3) & 1) * 8) * 48 + ((lid >> 4) & 1) * 16);
    const uint32_t bOff =
        (uint32_t)(((lid & 7) + ((lid >> 4) & 1) * 8) * 48 + ((lid >> 3) & 1) * 16);
    const uint32_t aHiS[2] = { smem_u32(Ahi[0]) + aOff, smem_u32(Ahi[1]) + aOff };
    const uint32_t aLoS[2] = { smem_u32(Alo[0]) + aOff, smem_u32(Alo[1]) + aOff };
    const uint32_t bHiS[2] = { smem_u32(Bhi[0]) + bOff, smem_u32(Bhi[1]) + bOff };
    const uint32_t bLoS[2] = { smem_u32(Blo[0]) + bOff, smem_u32(Blo[1]) + bOff };

    // acc[f*8 + nt][4]: f = m-frag (0..1), nt = n8 tile (0..7)
    float acc[16][4];
#pragma unroll
    for (int i = 0; i < 16; ++i)
#pragma unroll
        for (int j = 0; j < 4; ++j) acc[i][j] = 0.f;

    int kcur = -1;
    float4 cw4;
    ushort4 cidx;

    auto prefetch = [&](int j, uint4& pAh, uint4& pAl, uint4& pBh, uint4& pBl) {
        const int ck0 = j * BKC;
        const size_t gi = (size_t)arow * CKK + ck0 + ahalf * 8;
        pAh = *(const uint4*)(g_Wph + gi);
        pAl = *(const uint4*)(g_Wpl + gi);

        const int kn = j >> 3;
        if (kn != kcur) {
            kcur = kn;
            const int t = (bimg9 + kn) * HW + pj;
            cw4 = __ldg(&g_w4[t]);
            cidx = __ldg(&g_idx[t]);
        }
        const int cbase = ((j & 7) * 16) + bh * 8;
        const float* __restrict__ xc = xb + (size_t)cbase * HW;
        unsigned short hu[8], lu[8];
#pragma unroll
        for (int j2 = 0; j2 < 8; ++j2) {
            const float v = cw4.x * __ldg(xc + cidx.x) + cw4.y * __ldg(xc + cidx.y)
                          + cw4.z * __ldg(xc + cidx.z) + cw4.w * __ldg(xc + cidx.w);
            bf16_split(v, hu[j2], lu[j2]);
            xc += HW;
        }
        pBh = make_uint4((uint32_t)hu[0] | ((uint32_t)hu[1] << 16),
                         (uint32_t)hu[2] | ((uint32_t)hu[3] << 16),
                         (uint32_t)hu[4] | ((uint32_t)hu[5] << 16),
                         (uint32_t)hu[6] | ((uint32_t)hu[7] << 16));
        pBl = make_uint4((uint32_t)lu[0] | ((uint32_t)lu[1] << 16),
                         (uint32_t)lu[2] | ((uint32_t)lu[3] << 16),
                         (uint32_t)lu[4] | ((uint32_t)lu[5] << 16),
                         (uint32_t)lu[6] | ((uint32_t)lu[7] << 16));
    };
    auto store_stage = [&](int dst, const uint4& pAh, const uint4& pAl,
                           const uint4& pBh, const uint4& pBl) {
        *(uint4*)(Ahi[dst] + arow * BSTU + ahalf * 8) = pAh;
        *(uint4*)(Alo[dst] + arow * BSTU + ahalf * 8) = pAl;
        *(uint4*)(Bhi[dst] + px * BSTU + bh * 8) = pBh;
        *(uint4*)(Blo[dst] + px * BSTU + bh * 8) = pBl;
    };

    {
        uint4 a0, a1, b0, b1;
        prefetch(0, a0, a1, b0, b1);
        store_stage(0, a0, a1, b0, b1);
    }
    __syncthreads();

    int s = 0;
    for (int it = 0; it < NIT; ++it) {
        uint4 pAh, pAl, pBh, pBl;
        const bool has_next = (it + 1 < NIT);
        if (has_next) prefetch(it + 1, pAh, pAl, pBh, pBl);

        // A frags: two 16-row tiles (m0, m0+16), hi & lo
        uint32_t fAh[2][4], fAl[2][4];
        ldm_x4(fAh[0], aHiS[s]);
        ldm_x4(fAh[1], aHiS[s] + 16 * 48);
        ldm_x4(fAl[0], aLoS[s]);
        ldm_x4(fAl[1], aLoS[s] + 16 * 48);

#pragma unroll
        for (int pt = 0; pt < 4; ++pt) {
            uint32_t fBh[4], fBl[4];
            const uint32_t boff = (uint32_t)((nq * 64 + pt * 16) * 48);
            ldm_x4(fBh, bHiS[s] + boff);
            ldm_x4(fBl, bLoS[s] + boff);
#pragma unroll
            for (int f = 0; f < 2; ++f) {
                mma_bf16(acc[f * 8 + 2 * pt], fAh[f], fBh[0], fBh[1]);
                mma_bf16(acc[f * 8 + 2 * pt], fAh[f], fBl[0], fBl[1]);
                mma_bf16(acc[f * 8 + 2 * pt], fAl[f], fBh[0], fBh[1]);
                mma_bf16(acc[f * 8 + 2 * pt + 1], fAh[f], fBh[2], fBh[3]);
                mma_bf16(acc[f * 8 + 2 * pt + 1], fAh[f], fBl[2], fBl[3]);
                mma_bf16(acc[f * 8 + 2 * pt + 1], fAl[f], fBh[2], fBh[3]);
            }
        }

        if (has_next) store_stage(s ^ 1, pAh, pAl, pBh, pBl);
        __syncthreads();
        s ^= 1;
    }

    // ---- epilogue ----
    const int r = lid >> 2;
    const int q = lid & 3;
#pragma unroll
    for (int f = 0; f < 2; ++f) {
        const int oA = m0 + f * 16 + r;
        const int oB = oA + 8;
        const float bvA = __ldg(bias + oA);
        const float bvB = __ldg(bias + oB);
        float* baseA = out + ((size_t)(bimg * OO + oA)) * HW + p0 + nq * 64 + 2 * q;
        float* baseB = out + ((size_t)(bimg * OO + oB)) * HW + p0 + nq * 64 + 2 * q;
#pragma unroll
        for (int nt = 0; nt < 8; ++nt) {
            const int ai = f * 8 + nt;
            float2 rA, rB;
            rA.x = acc[ai][0] + bvA; rA.y = acc[ai][1] + bvA;
            rB.x = acc[ai][2] + bvB; rB.y = acc[ai][3] + bvB;
            *(float2*)(baseA + nt * 8) = rA;
            *(float2*)(baseB + nt * 8) = rB;
        }
    }
}

// ============================================================================
extern "C" void kernel_launch(void* const* d_in, const int* in_sizes, int n_in,
                              void* d_out, int out_size) {
    const float* x      = (const float*)d_in[0];   // (8,128,64,64)
    const float* w_om   = (const float*)d_in[1];   // (27,128,3,3)
    const float* b_om   = (const float*)d_in[2];   // (27,)
    const float* weight = (const float*)d_in[3];   // (128,128,3,3)
    const float* bias   = (const float*)d_in[4];   // (128,)
    float* out = (float*)d_out;                    // (8,128,64,64)

    prep_w<<<(OO * CKK + 255) / 256, 256>>>(weight);
    prep_wom<<<(OMM * CKK + 255) / 256, 256>>>(w_om);
    om_gemm<<<NPIX / 128, 256>>>(x);
    om_final<<<NPIX / 256, 256>>>(b_om);
    gemm_mma<<<NPIX / 128, 256>>>(x, bias, out);
}